// round 7
// baseline (speedup 1.0000x reference)
#include <cuda_runtime.h>
#include <math.h>

// ---------------------------------------------------------------------------
// FraudNATHybridModel — R6: R5 packed-f32x2 convs with the float4-zero-fill
// alignment bug fixed (sh1p was float2/8B-aligned, cast to float4 -> ST.128
// misaligned trap). All packed operands still come directly from LDS.64.
// ---------------------------------------------------------------------------

#define BMAX 8192

__device__ float2 g_U[256];
__device__ float  g_z[BMAX * 4];
__device__ float  g_coef[8];

#define UNPACK2(lo, hi, in) \
    do { unsigned _ulo, _uhi; \
         asm("mov.b64 {%0, %1}, %2;" : "=r"(_ulo), "=r"(_uhi) : "l"(in)); \
         lo = __uint_as_float(_ulo); hi = __uint_as_float(_uhi); } while (0)
#define FMA2(acc, a, b) \
    asm("fma.rn.f32x2 %0, %1, %2, %0;" : "+l"(acc) : "l"(a), "l"(b))

__device__ __forceinline__ unsigned long long lds64(const void* p) {
    unsigned long long v;
    unsigned a = (unsigned)__cvta_generic_to_shared(p);
    asm volatile("ld.shared.b64 %0, [%1];" : "=l"(v) : "r"(a));
    return v;
}

__device__ __forceinline__ float2 cmul(float2 a, float2 b) {
    return make_float2(a.x * b.x - a.y * b.y, a.x * b.y + a.y * b.x);
}
__device__ __forceinline__ float2 cadd(float2 a, float2 b) {
    return make_float2(a.x + b.x, a.y + b.y);
}
__device__ __forceinline__ float2 cfma_(float2 a, float2 b, float2 c) {
    c.x += a.x * b.x - a.y * b.y;
    c.y += a.x * b.y + a.y * b.x;
    return c;
}

// ------------------------- MT19937 (numpy legacy) --------------------------
__device__ unsigned mt_next(unsigned* mt, int* mti) {
    if (*mti >= 624) {
        for (int i = 0; i < 624; i++) {
            unsigned y = (mt[i] & 0x80000000u) | (mt[(i + 1) % 624] & 0x7fffffffu);
            unsigned v = mt[(i + 397) % 624] ^ (y >> 1);
            if (y & 1u) v ^= 0x9908b0dfu;
            mt[i] = v;
        }
        *mti = 0;
    }
    unsigned y = mt[(*mti)++];
    y ^= y >> 11;
    y ^= (y << 7) & 0x9d2c5680u;
    y ^= (y << 15) & 0xefc60000u;
    y ^= y >> 18;
    return y;
}

__device__ void ap1(float2* s, int w, float2 u00, float2 u01, float2 u10, float2 u11) {
    int m = 8 >> w;
    for (int i = 0; i < 16; i++) {
        if (!(i & m)) {
            float2 a = s[i], b = s[i | m];
            s[i]     = cadd(cmul(u00, a), cmul(u01, b));
            s[i | m] = cadd(cmul(u10, a), cmul(u11, b));
        }
    }
}
__device__ void ap2(float2* s, int wc, int wt, float2 u00, float2 u01, float2 u10, float2 u11) {
    int mc = 8 >> wc, mt2 = 8 >> wt;
    for (int i = 0; i < 16; i++) {
        if ((i & mc) && !(i & mt2)) {
            float2 a = s[i], b = s[i | mt2];
            s[i]       = cadd(cmul(u00, a), cmul(u01, b));
            s[i | mt2] = cadd(cmul(u10, a), cmul(u11, b));
        }
    }
}

// ------------------------- K0: build U_post --------------------------------
__global__ void k_setup(const float* __restrict__ gate_params,
                        const float* __restrict__ rand_params) {
    __shared__ unsigned smt[624];
    __shared__ int sg[50], sw0[50], sw1[50], sp[50];
    int tid = threadIdx.x;

    if (tid == 0) {
        smt[0] = 12345u;
        for (int i = 1; i < 624; i++)
            smt[i] = 1812433253u * (smt[i - 1] ^ (smt[i - 1] >> 30)) + (unsigned)i;
        int mti = 624;
        int p = 0;
        for (int k = 0; k < 50; k++) {
            unsigned g;
            do { g = mt_next(smt, &mti) & 7u; } while (g > 4u);
            int w0, w1 = -1;
            if (g >= 3u) {
                int arr[4] = {0, 1, 2, 3};
                for (int i = 3; i >= 1; --i) {
                    unsigned mask = (unsigned)i;
                    mask |= mask >> 1; mask |= mask >> 2; mask |= mask >> 4;
                    unsigned j;
                    do { j = mt_next(smt, &mti) & mask; } while (j > (unsigned)i);
                    int t = arr[i]; arr[i] = arr[j]; arr[j] = t;
                }
                w0 = arr[0]; w1 = arr[1];
            } else {
                w0 = (int)(mt_next(smt, &mti) & 3u);
            }
            sg[k] = (int)g; sw0[k] = w0; sw1[k] = w1;
            sp[k] = (g == 4u) ? -1 : p++;
        }
    }
    __syncthreads();

    if (tid < 16) {
        float2 st[16];
        for (int i = 0; i < 16; i++) st[i] = make_float2(i == tid ? 1.f : 0.f, 0.f);

        for (int k = 0; k < 50; k++) {
            int g = sg[k], w0 = sw0[k], w1 = sw1[k];
            float t = (sp[k] >= 0) ? rand_params[sp[k]] : 0.f;
            float sn, cs;
            sincosf(0.5f * t, &sn, &cs);
            if (g == 0) {
                ap1(st, w0, make_float2(cs, 0), make_float2(0, -sn),
                            make_float2(0, -sn), make_float2(cs, 0));
            } else if (g == 1) {
                ap1(st, w0, make_float2(cs, 0), make_float2(-sn, 0),
                            make_float2(sn, 0), make_float2(cs, 0));
            } else if (g == 2) {
                ap1(st, w0, make_float2(cs, -sn), make_float2(0, 0),
                            make_float2(0, 0), make_float2(cs, sn));
            } else if (g == 3) {
                ap2(st, w0, w1, make_float2(cs, 0), make_float2(0, -sn),
                                make_float2(0, -sn), make_float2(cs, 0));
            } else {
                ap2(st, w0, w1, make_float2(0, 0), make_float2(1, 0),
                                make_float2(1, 0), make_float2(0, 0));
            }
        }
        float sn, cs;
        sincosf(0.5f * gate_params[0], &sn, &cs);
        ap1(st, 0, make_float2(cs, 0), make_float2(0, -sn), make_float2(0, -sn), make_float2(cs, 0));
        sincosf(0.5f * gate_params[1], &sn, &cs);
        ap1(st, 1, make_float2(cs, 0), make_float2(-sn, 0), make_float2(sn, 0), make_float2(cs, 0));
        sincosf(0.5f * gate_params[2], &sn, &cs);
        ap1(st, 3, make_float2(cs, -sn), make_float2(0, 0), make_float2(0, 0), make_float2(cs, sn));
        sincosf(0.5f * gate_params[3], &sn, &cs);
        ap2(st, 0, 2, make_float2(cs, 0), make_float2(0, -sn), make_float2(0, -sn), make_float2(cs, 0));
        const float r = 0.70710678118654752f;
        ap1(st, 3, make_float2(r, 0), make_float2(r, 0), make_float2(r, 0), make_float2(-r, 0));
        ap1(st, 2, make_float2(0.5f, 0.5f), make_float2(0.5f, -0.5f),
                   make_float2(0.5f, -0.5f), make_float2(0.5f, 0.5f));
        ap2(st, 3, 0, make_float2(0, 0), make_float2(1, 0), make_float2(1, 0), make_float2(0, 0));

        for (int i = 0; i < 16; i++) g_U[i * 16 + tid] = st[i];
    }
}

// ------------------------- K1: fused per-image pipeline --------------------
// sxp[j][c]: (x[j-1][c-1], x[j][c-1]) vertical input pairs, zero-padded.
// sh1p[ic*16 + y+1][c]: (m,m) duplicated conv1 pooled values, zero-padded.
// sw2p[k][cp]: (w2[2cp][k], w2[2cp+1][k]) channel-pair weights.
__global__ __launch_bounds__(128) void k_main(const float* __restrict__ x,
                                              const float* __restrict__ w1,
                                              const float* __restrict__ b1,
                                              const float* __restrict__ w2,
                                              const float* __restrict__ b2) {
    __shared__ __align__(16) float2 sxp[29][31];
    __shared__ __align__(16) float2 sh1p[128][17];
    __shared__ float2 sw1p[72];          // (w,w)
    __shared__ float2 sb1p[8];           // (b,b)
    __shared__ float2 sw2p[72][8];
    __shared__ float2 sb2p[8];           // (b_c0, b_c1)
    __shared__ float shm[16 * 14 * 7];
    __shared__ float spart[112];
    __shared__ float spool[16];
    __shared__ float2 sv[8];
    __shared__ float2 sphi[16];

    int tid = threadIdx.x;
    int b = blockIdx.x;
    const float* xb = x + (size_t)b * 784;

    // ---- zero padded arrays (float2 stores only: 8B-safe) ----
    {
        float2 z2 = make_float2(0.f, 0.f);
        float2* p1 = &sxp[0][0];
        for (int i = tid; i < 29 * 31; i += 128) p1[i] = z2;
        float2* p2 = &sh1p[0][0];
        for (int i = tid; i < 128 * 17; i += 128) p2[i] = z2;
    }
    // ---- stage weights ----
    for (int i = tid; i < 72; i += 128) { float w = w1[i]; sw1p[i] = make_float2(w, w); }
    if (tid < 8)  { float v = b1[tid]; sb1p[tid] = make_float2(v, v); }
    for (int i = tid; i < 576; i += 128) {
        int k = i >> 3, cp = i & 7;
        sw2p[k][cp] = make_float2(w2[(2 * cp) * 72 + k], w2[(2 * cp + 1) * 72 + k]);
    }
    if (tid < 8)  sb2p[tid] = make_float2(b2[2 * tid], b2[2 * tid + 1]);
    __syncthreads();

    // ---- scatter input into vertical pairs ----
    for (int i = tid; i < 784; i += 128) {
        int r = i / 28, c = i % 28;
        float v = xb[i];
        sxp[r + 1][c + 1].x = v;
        sxp[r][c + 1].y = v;
    }
    __syncthreads();

    // ---- conv1 (packed vertical row pairs) + relu + maxpool -> sh1p ----
    if (tid < 112) {
        int c = tid / 14, y = tid % 14;
        unsigned long long wp[9];
#pragma unroll
        for (int k = 0; k < 9; k++) wp[k] = lds64(&sw1p[c * 9 + k]);
        unsigned long long bias2 = lds64(&sb1p[c]);
        float pooled[14];
#pragma unroll
        for (int h = 0; h < 2; h++) {
            unsigned long long cr[14];
#pragma unroll
            for (int i = 0; i < 14; i++) cr[i] = bias2;
#pragma unroll
            for (int ky = 0; ky < 3; ky++) {
                int j = 2 * y + ky;
                unsigned long long rp[16];
#pragma unroll
                for (int i = 0; i < 16; i++) rp[i] = lds64(&sxp[j][14 * h + i]);
#pragma unroll
                for (int kx = 0; kx < 3; kx++) {
                    unsigned long long w = wp[ky * 3 + kx];
#pragma unroll
                    for (int i = 0; i < 14; i++) FMA2(cr[i], w, rp[i + kx]);
                }
            }
#pragma unroll
            for (int o = 0; o < 7; o++) {
                float l0, h0, l1, h1;
                UNPACK2(l0, h0, cr[2 * o]);
                UNPACK2(l1, h1, cr[2 * o + 1]);
                pooled[h * 7 + o] = fmaxf(fmaxf(fmaxf(l0, h0), fmaxf(l1, h1)), 0.f);
            }
        }
        float2* row = sh1p[c * 16 + y + 1];
#pragma unroll
        for (int i = 0; i < 14; i++) row[i + 1] = make_float2(pooled[i], pooled[i]);
    }
    __syncthreads();

    // ---- conv2 (packed channel pairs) + horizontal pair-max -> shm ----
    if (tid < 112) {
        int cp = tid / 14, y = tid % 14;
        unsigned long long acc[14];
        {
            unsigned long long bias2 = lds64(&sb2p[cp]);
#pragma unroll
            for (int i = 0; i < 14; i++) acc[i] = bias2;
        }
#pragma unroll
        for (int ic = 0; ic < 8; ic++) {
#pragma unroll
            for (int ky = 0; ky < 3; ky++) {
                const float2* rowp = sh1p[ic * 16 + y + ky];
                unsigned long long rp[16];
#pragma unroll
                for (int i = 0; i < 16; i++) rp[i] = lds64(&rowp[i]);
#pragma unroll
                for (int kx = 0; kx < 3; kx++) {
                    unsigned long long w = lds64(&sw2p[ic * 9 + ky * 3 + kx][cp]);
#pragma unroll
                    for (int i = 0; i < 14; i++) FMA2(acc[i], w, rp[i + kx]);
                }
            }
        }
#pragma unroll
        for (int o = 0; o < 7; o++) {
            float a0l, a1l, a0h, a1h;
            UNPACK2(a0l, a1l, acc[2 * o]);
            UNPACK2(a0h, a1h, acc[2 * o + 1]);
            shm[((2 * cp) * 14 + y) * 7 + o]     = fmaxf(a0l, a0h);
            shm[((2 * cp + 1) * 14 + y) * 7 + o] = fmaxf(a1l, a1h);
        }
    }
    __syncthreads();

    // ---- vertical max of row pairs + relu + row sum -> spart ----
    if (tid < 112) {
        int c = tid / 7, y2 = tid % 7;
        const float* r0 = &shm[(c * 14 + 2 * y2) * 7];
        const float* r1 = r0 + 7;
        float psum = 0.f;
#pragma unroll
        for (int i = 0; i < 7; i++)
            psum += fmaxf(fmaxf(r0[i], r1[i]), 0.f);
        spart[c * 7 + y2] = psum;
    }
    __syncthreads();

    if (tid < 16) {
        float s = 0.f;
#pragma unroll
        for (int j = 0; j < 7; j++) s += spart[tid * 7 + j];
        spool[tid] = s * (1.f / 49.f);
    }
    __syncthreads();

    // ---- quantum: product-state encoder, psi = U_post * phi, Z expectations
    if (tid < 32) {
        int lane = tid;
        if (lane < 4) {
            float aa = spool[lane], bb = spool[4 + lane],
                  cc = spool[8 + lane], dd = spool[12 + lane];
            float sa, ca, sb, cb, sc, ccs, sd, cd;
            sincosf(0.5f * aa, &sa, &ca);
            sincosf(0.5f * bb, &sb, &cb);
            sincosf(0.5f * cc, &sc, &ccs);
            sincosf(0.5f * dd, &sd, &cd);
            float2 v0 = make_float2(ca * cb, -ca * sb);
            float2 v1 = make_float2(sa * cb, sa * sb);
            float2 t0 = make_float2(ccs * v0.x + sc * v1.y, ccs * v0.y - sc * v1.x);
            float2 t1 = make_float2(sc * v0.y + ccs * v1.x, -sc * v0.x + ccs * v1.y);
            float2 u0 = make_float2(cd * t0.x - sd * t1.x, cd * t0.y - sd * t1.y);
            float2 u1 = make_float2(sd * t0.x + cd * t1.x, sd * t0.y + cd * t1.y);
            sv[2 * lane] = u0;
            sv[2 * lane + 1] = u1;
        }
        __syncwarp();
        if (lane < 16) {
            float2 f0 = sv[0 + ((lane >> 3) & 1)];
            float2 f1 = sv[2 + ((lane >> 2) & 1)];
            float2 f2 = sv[4 + ((lane >> 1) & 1)];
            float2 f3 = sv[6 + (lane & 1)];
            sphi[lane] = cmul(cmul(f0, f1), cmul(f2, f3));
        }
        __syncwarp();
        float p = 0.f;
        if (lane < 16) {
            float2 psi = make_float2(0.f, 0.f);
#pragma unroll
            for (int j = 0; j < 16; j++) psi = cfma_(g_U[lane * 16 + j], sphi[j], psi);
            p = psi.x * psi.x + psi.y * psi.y;
        }
#pragma unroll
        for (int w = 0; w < 4; w++) {
            float sgn = ((lane >> (3 - w)) & 1) ? -p : p;
#pragma unroll
            for (int off = 16; off > 0; off >>= 1)
                sgn += __shfl_xor_sync(0xffffffffu, sgn, off);
            if (lane == 0) g_z[b * 4 + w] = sgn;
        }
    }
}

// ------------------------- K2: BN stats + fold into coefficients -----------
__global__ void k_reduce(const float* __restrict__ gam, const float* __restrict__ bet,
                         const float* __restrict__ fcw, const float* __restrict__ fcb,
                         int B) {
    __shared__ double red[256 * 8];
    int tid = threadIdx.x;
    double sm[4] = {0, 0, 0, 0}, sq[4] = {0, 0, 0, 0};
    for (int r = tid; r < B; r += 256) {
#pragma unroll
        for (int j = 0; j < 4; j++) {
            double v = (double)g_z[r * 4 + j];
            sm[j] += v;
            sq[j] += v * v;
        }
    }
#pragma unroll
    for (int j = 0; j < 4; j++) { red[tid * 8 + j] = sm[j]; red[tid * 8 + 4 + j] = sq[j]; }
    __syncthreads();
    for (int s = 128; s > 0; s >>= 1) {
        if (tid < s) {
#pragma unroll
            for (int j = 0; j < 8; j++) red[tid * 8 + j] += red[(tid + s) * 8 + j];
        }
        __syncthreads();
    }
    if (tid == 0) {
        double invB = 1.0 / (double)B;
        double csum = (double)fcb[0];
        for (int j = 0; j < 4; j++) {
            double mu = red[j] * invB;
            double var = red[4 + j] * invB - mu * mu;
            double sc = (double)gam[j] / sqrt(var + 1e-5);
            g_coef[j] = (float)((double)fcw[j] * sc);
            csum += (double)fcw[j] * ((double)bet[j] - mu * sc);
        }
        g_coef[4] = (float)csum;
    }
}

// ------------------------- K3: final output --------------------------------
__global__ void k_final(float* __restrict__ out, int B) {
    int b = blockIdx.x * blockDim.x + threadIdx.x;
    if (b < B) {
        out[b] = g_coef[4]
               + g_coef[0] * g_z[b * 4 + 0]
               + g_coef[1] * g_z[b * 4 + 1]
               + g_coef[2] * g_z[b * 4 + 2]
               + g_coef[3] * g_z[b * 4 + 3];
    }
}

extern "C" void kernel_launch(void* const* d_in, const int* in_sizes, int n_in,
                              void* d_out, int out_size) {
    const float* x   = (const float*)d_in[0];
    const float* c1w = (const float*)d_in[1];
    const float* c1b = (const float*)d_in[2];
    const float* c2w = (const float*)d_in[3];
    const float* c2b = (const float*)d_in[4];
    const float* gp  = (const float*)d_in[5];
    const float* rp  = (const float*)d_in[6];
    const float* gam = (const float*)d_in[7];
    const float* bet = (const float*)d_in[8];
    const float* fcw = (const float*)d_in[9];
    const float* fcb = (const float*)d_in[10];

    int B = in_sizes[0] / 784;
    if (B > BMAX) B = BMAX;

    k_setup<<<1, 32>>>(gp, rp);
    k_main<<<B, 128>>>(x, c1w, c1b, c2w, c2b);
    k_reduce<<<1, 256>>>(gam, bet, fcw, fcb, B);
    k_final<<<(B + 255) / 256, 256>>>((float*)d_out, B);
}

// round 8
// speedup vs baseline: 1.0703x; 1.0703x over previous
#include <cuda_runtime.h>
#include <math.h>

// ---------------------------------------------------------------------------
// FraudNATHybridModel — R8: hybrid of R4/R6 lessons.
//  conv1: packed vertical row-pairs (f32x2), inputs via LDS.64 pairs (R6).
//  conv2: channel-pair f32x2 accumulators, NON-duplicated zero-padded sh1
//         (LDS.32 inputs + ALU-pipe packs), stride-17 rows (conflict-free),
//         zero guards -> pure straight-line code.
// ---------------------------------------------------------------------------

#define BMAX 8192

__device__ float2 g_U[256];
__device__ float  g_z[BMAX * 4];
__device__ float  g_coef[8];

#define PACK2(out, lo, hi) \
    asm("mov.b64 %0, {%1, %2};" : "=l"(out) : "r"(__float_as_uint(lo)), "r"(__float_as_uint(hi)))
#define UNPACK2(lo, hi, in) \
    do { unsigned _ulo, _uhi; \
         asm("mov.b64 {%0, %1}, %2;" : "=r"(_ulo), "=r"(_uhi) : "l"(in)); \
         lo = __uint_as_float(_ulo); hi = __uint_as_float(_uhi); } while (0)
#define FMA2(acc, a, b) \
    asm("fma.rn.f32x2 %0, %1, %2, %0;" : "+l"(acc) : "l"(a), "l"(b))

__device__ __forceinline__ unsigned long long lds64(const void* p) {
    unsigned long long v;
    unsigned a = (unsigned)__cvta_generic_to_shared(p);
    asm("ld.shared.b64 %0, [%1];" : "=l"(v) : "r"(a));
    return v;
}

__device__ __forceinline__ float2 cmul(float2 a, float2 b) {
    return make_float2(a.x * b.x - a.y * b.y, a.x * b.y + a.y * b.x);
}
__device__ __forceinline__ float2 cadd(float2 a, float2 b) {
    return make_float2(a.x + b.x, a.y + b.y);
}
__device__ __forceinline__ float2 cfma_(float2 a, float2 b, float2 c) {
    c.x += a.x * b.x - a.y * b.y;
    c.y += a.x * b.y + a.y * b.x;
    return c;
}

// ------------------------- MT19937 (numpy legacy) --------------------------
__device__ unsigned mt_next(unsigned* mt, int* mti) {
    if (*mti >= 624) {
        for (int i = 0; i < 624; i++) {
            unsigned y = (mt[i] & 0x80000000u) | (mt[(i + 1) % 624] & 0x7fffffffu);
            unsigned v = mt[(i + 397) % 624] ^ (y >> 1);
            if (y & 1u) v ^= 0x9908b0dfu;
            mt[i] = v;
        }
        *mti = 0;
    }
    unsigned y = mt[(*mti)++];
    y ^= y >> 11;
    y ^= (y << 7) & 0x9d2c5680u;
    y ^= (y << 15) & 0xefc60000u;
    y ^= y >> 18;
    return y;
}

__device__ void ap1(float2* s, int w, float2 u00, float2 u01, float2 u10, float2 u11) {
    int m = 8 >> w;
    for (int i = 0; i < 16; i++) {
        if (!(i & m)) {
            float2 a = s[i], b = s[i | m];
            s[i]     = cadd(cmul(u00, a), cmul(u01, b));
            s[i | m] = cadd(cmul(u10, a), cmul(u11, b));
        }
    }
}
__device__ void ap2(float2* s, int wc, int wt, float2 u00, float2 u01, float2 u10, float2 u11) {
    int mc = 8 >> wc, mt2 = 8 >> wt;
    for (int i = 0; i < 16; i++) {
        if ((i & mc) && !(i & mt2)) {
            float2 a = s[i], b = s[i | mt2];
            s[i]       = cadd(cmul(u00, a), cmul(u01, b));
            s[i | mt2] = cadd(cmul(u10, a), cmul(u11, b));
        }
    }
}

// ------------------------- K0: build U_post --------------------------------
__global__ void k_setup(const float* __restrict__ gate_params,
                        const float* __restrict__ rand_params) {
    __shared__ unsigned smt[624];
    __shared__ int sg[50], sw0[50], sw1[50], sp[50];
    int tid = threadIdx.x;

    if (tid == 0) {
        smt[0] = 12345u;
        for (int i = 1; i < 624; i++)
            smt[i] = 1812433253u * (smt[i - 1] ^ (smt[i - 1] >> 30)) + (unsigned)i;
        int mti = 624;
        int p = 0;
        for (int k = 0; k < 50; k++) {
            unsigned g;
            do { g = mt_next(smt, &mti) & 7u; } while (g > 4u);
            int w0, w1 = -1;
            if (g >= 3u) {
                int arr[4] = {0, 1, 2, 3};
                for (int i = 3; i >= 1; --i) {
                    unsigned mask = (unsigned)i;
                    mask |= mask >> 1; mask |= mask >> 2; mask |= mask >> 4;
                    unsigned j;
                    do { j = mt_next(smt, &mti) & mask; } while (j > (unsigned)i);
                    int t = arr[i]; arr[i] = arr[j]; arr[j] = t;
                }
                w0 = arr[0]; w1 = arr[1];
            } else {
                w0 = (int)(mt_next(smt, &mti) & 3u);
            }
            sg[k] = (int)g; sw0[k] = w0; sw1[k] = w1;
            sp[k] = (g == 4u) ? -1 : p++;
        }
    }
    __syncthreads();

    if (tid < 16) {
        float2 st[16];
        for (int i = 0; i < 16; i++) st[i] = make_float2(i == tid ? 1.f : 0.f, 0.f);

        for (int k = 0; k < 50; k++) {
            int g = sg[k], w0 = sw0[k], w1 = sw1[k];
            float t = (sp[k] >= 0) ? rand_params[sp[k]] : 0.f;
            float sn, cs;
            sincosf(0.5f * t, &sn, &cs);
            if (g == 0) {
                ap1(st, w0, make_float2(cs, 0), make_float2(0, -sn),
                            make_float2(0, -sn), make_float2(cs, 0));
            } else if (g == 1) {
                ap1(st, w0, make_float2(cs, 0), make_float2(-sn, 0),
                            make_float2(sn, 0), make_float2(cs, 0));
            } else if (g == 2) {
                ap1(st, w0, make_float2(cs, -sn), make_float2(0, 0),
                            make_float2(0, 0), make_float2(cs, sn));
            } else if (g == 3) {
                ap2(st, w0, w1, make_float2(cs, 0), make_float2(0, -sn),
                                make_float2(0, -sn), make_float2(cs, 0));
            } else {
                ap2(st, w0, w1, make_float2(0, 0), make_float2(1, 0),
                                make_float2(1, 0), make_float2(0, 0));
            }
        }
        float sn, cs;
        sincosf(0.5f * gate_params[0], &sn, &cs);
        ap1(st, 0, make_float2(cs, 0), make_float2(0, -sn), make_float2(0, -sn), make_float2(cs, 0));
        sincosf(0.5f * gate_params[1], &sn, &cs);
        ap1(st, 1, make_float2(cs, 0), make_float2(-sn, 0), make_float2(sn, 0), make_float2(cs, 0));
        sincosf(0.5f * gate_params[2], &sn, &cs);
        ap1(st, 3, make_float2(cs, -sn), make_float2(0, 0), make_float2(0, 0), make_float2(cs, sn));
        sincosf(0.5f * gate_params[3], &sn, &cs);
        ap2(st, 0, 2, make_float2(cs, 0), make_float2(0, -sn), make_float2(0, -sn), make_float2(cs, 0));
        const float r = 0.70710678118654752f;
        ap1(st, 3, make_float2(r, 0), make_float2(r, 0), make_float2(r, 0), make_float2(-r, 0));
        ap1(st, 2, make_float2(0.5f, 0.5f), make_float2(0.5f, -0.5f),
                   make_float2(0.5f, -0.5f), make_float2(0.5f, 0.5f));
        ap2(st, 3, 0, make_float2(0, 0), make_float2(1, 0), make_float2(1, 0), make_float2(0, 0));

        for (int i = 0; i < 16; i++) g_U[i * 16 + tid] = st[i];
    }
}

// ------------------------- K1: fused per-image pipeline --------------------
// sxp[j][c] = (x[j-1][c-1], x[j][c-1]), zero-padded  (conv1 vertical pairs)
// sh1[ic][r][c] plain floats, rows/cols 0 & 15 zero, row stride 17
// sw2p[k][cp] = (w2[2cp][k], w2[2cp+1][k]) channel-pair weights
__global__ __launch_bounds__(128) void k_main(const float* __restrict__ x,
                                              const float* __restrict__ w1,
                                              const float* __restrict__ b1,
                                              const float* __restrict__ w2,
                                              const float* __restrict__ b2) {
    __shared__ __align__(16) float2 sxp[29][31];
    __shared__ float sh1[8 * 16 * 17];   // [ic][row 0..15][col 0..16], stride 17
    __shared__ float2 sw1p[72];          // (w,w)
    __shared__ float2 sb1p[8];           // (b,b)
    __shared__ float2 sw2p[72][8];
    __shared__ float2 sb2p[8];           // (b_c0, b_c1)
    __shared__ float shm[16 * 14 * 7];
    __shared__ float spart[112];
    __shared__ float spool[16];
    __shared__ float2 sv[8];
    __shared__ float2 sphi[16];

    int tid = threadIdx.x;
    int b = blockIdx.x;
    const float* xb = x + (size_t)b * 784;

    // ---- zero padded arrays ----
    {
        float2 z2 = make_float2(0.f, 0.f);
        float2* p1 = &sxp[0][0];
        for (int i = tid; i < 29 * 31; i += 128) p1[i] = z2;
        for (int i = tid; i < 8 * 16 * 17; i += 128) sh1[i] = 0.f;
    }
    // ---- stage weights ----
    for (int i = tid; i < 72; i += 128) { float w = w1[i]; sw1p[i] = make_float2(w, w); }
    if (tid < 8)  { float v = b1[tid]; sb1p[tid] = make_float2(v, v); }
    for (int i = tid; i < 576; i += 128) {
        int k = i >> 3, cp = i & 7;
        sw2p[k][cp] = make_float2(w2[(2 * cp) * 72 + k], w2[(2 * cp + 1) * 72 + k]);
    }
    if (tid < 8)  sb2p[tid] = make_float2(b2[2 * tid], b2[2 * tid + 1]);
    __syncthreads();

    // ---- scatter input into vertical pairs ----
    for (int i = tid; i < 784; i += 128) {
        int r = i / 28, c = i % 28;
        float v = xb[i];
        sxp[r + 1][c + 1].x = v;
        sxp[r][c + 1].y = v;
    }
    __syncthreads();

    // ---- conv1 (packed vertical row pairs) + relu + maxpool -> sh1 ----
    if (tid < 112) {
        int c = tid / 14, y = tid % 14;
        unsigned long long wp[9];
#pragma unroll
        for (int k = 0; k < 9; k++) wp[k] = lds64(&sw1p[c * 9 + k]);
        unsigned long long bias2 = lds64(&sb1p[c]);
        float pooled[14];
#pragma unroll
        for (int h = 0; h < 2; h++) {
            unsigned long long cr[14];
#pragma unroll
            for (int i = 0; i < 14; i++) cr[i] = bias2;
#pragma unroll
            for (int ky = 0; ky < 3; ky++) {
                int j = 2 * y + ky;
                unsigned long long rp[16];
#pragma unroll
                for (int i = 0; i < 16; i++) rp[i] = lds64(&sxp[j][14 * h + i]);
#pragma unroll
                for (int kx = 0; kx < 3; kx++) {
                    unsigned long long w = wp[ky * 3 + kx];
#pragma unroll
                    for (int i = 0; i < 14; i++) FMA2(cr[i], w, rp[i + kx]);
                }
            }
#pragma unroll
            for (int o = 0; o < 7; o++) {
                float l0, h0, l1, h1;
                UNPACK2(l0, h0, cr[2 * o]);
                UNPACK2(l1, h1, cr[2 * o + 1]);
                pooled[h * 7 + o] = fmaxf(fmaxf(fmaxf(l0, h0), fmaxf(l1, h1)), 0.f);
            }
        }
        // write row y+1, cols 1..14 (borders stay zero)
        float* row = &sh1[(c * 16 + y + 1) * 17];
#pragma unroll
        for (int i = 0; i < 14; i++) row[i + 1] = pooled[i];
    }
    __syncthreads();

    // ---- conv2: channel-pair f32x2, LDS.32 inputs + packs, no guards ----
    if (tid < 112) {
        int cp = tid / 14, y = tid % 14;
        unsigned long long acc[14];
        {
            unsigned long long bias2 = lds64(&sb2p[cp]);
#pragma unroll
            for (int i = 0; i < 14; i++) acc[i] = bias2;
        }
#pragma unroll
        for (int ic = 0; ic < 8; ic++) {
#pragma unroll
            for (int ky = 0; ky < 3; ky++) {
                // stored row y+ky in 0..15 (rows 0,15 are zero -> no branch)
                const float* row = &sh1[(ic * 16 + y + ky) * 17];
                unsigned long long rp[16];
#pragma unroll
                for (int i = 0; i < 16; i++) {
                    float v = row[i];
                    PACK2(rp[i], v, v);
                }
#pragma unroll
                for (int kx = 0; kx < 3; kx++) {
                    unsigned long long w = lds64(&sw2p[ic * 9 + ky * 3 + kx][cp]);
#pragma unroll
                    for (int i = 0; i < 14; i++) FMA2(acc[i], w, rp[i + kx]);
                }
            }
        }
#pragma unroll
        for (int o = 0; o < 7; o++) {
            float a0l, a1l, a0h, a1h;
            UNPACK2(a0l, a1l, acc[2 * o]);
            UNPACK2(a0h, a1h, acc[2 * o + 1]);
            shm[((2 * cp) * 14 + y) * 7 + o]     = fmaxf(a0l, a0h);
            shm[((2 * cp + 1) * 14 + y) * 7 + o] = fmaxf(a1l, a1h);
        }
    }
    __syncthreads();

    // ---- vertical max of row pairs + relu + row sum -> spart ----
    if (tid < 112) {
        int c = tid / 7, y2 = tid % 7;
        const float* r0 = &shm[(c * 14 + 2 * y2) * 7];
        const float* r1 = r0 + 7;
        float psum = 0.f;
#pragma unroll
        for (int i = 0; i < 7; i++)
            psum += fmaxf(fmaxf(r0[i], r1[i]), 0.f);
        spart[c * 7 + y2] = psum;
    }
    __syncthreads();

    if (tid < 16) {
        float s = 0.f;
#pragma unroll
        for (int j = 0; j < 7; j++) s += spart[tid * 7 + j];
        spool[tid] = s * (1.f / 49.f);
    }
    __syncthreads();

    // ---- quantum: product-state encoder, psi = U_post * phi, Z expectations
    if (tid < 32) {
        int lane = tid;
        if (lane < 4) {
            float aa = spool[lane], bb = spool[4 + lane],
                  cc = spool[8 + lane], dd = spool[12 + lane];
            float sa, ca, sb, cb, sc, ccs, sd, cd;
            sincosf(0.5f * aa, &sa, &ca);
            sincosf(0.5f * bb, &sb, &cb);
            sincosf(0.5f * cc, &sc, &ccs);
            sincosf(0.5f * dd, &sd, &cd);
            float2 v0 = make_float2(ca * cb, -ca * sb);
            float2 v1 = make_float2(sa * cb, sa * sb);
            float2 t0 = make_float2(ccs * v0.x + sc * v1.y, ccs * v0.y - sc * v1.x);
            float2 t1 = make_float2(sc * v0.y + ccs * v1.x, -sc * v0.x + ccs * v1.y);
            float2 u0 = make_float2(cd * t0.x - sd * t1.x, cd * t0.y - sd * t1.y);
            float2 u1 = make_float2(sd * t0.x + cd * t1.x, sd * t0.y + cd * t1.y);
            sv[2 * lane] = u0;
            sv[2 * lane + 1] = u1;
        }
        __syncwarp();
        if (lane < 16) {
            float2 f0 = sv[0 + ((lane >> 3) & 1)];
            float2 f1 = sv[2 + ((lane >> 2) & 1)];
            float2 f2 = sv[4 + ((lane >> 1) & 1)];
            float2 f3 = sv[6 + (lane & 1)];
            sphi[lane] = cmul(cmul(f0, f1), cmul(f2, f3));
        }
        __syncwarp();
        float p = 0.f;
        if (lane < 16) {
            float2 psi = make_float2(0.f, 0.f);
#pragma unroll
            for (int j = 0; j < 16; j++) psi = cfma_(g_U[lane * 16 + j], sphi[j], psi);
            p = psi.x * psi.x + psi.y * psi.y;
        }
#pragma unroll
        for (int w = 0; w < 4; w++) {
            float sgn = ((lane >> (3 - w)) & 1) ? -p : p;
#pragma unroll
            for (int off = 16; off > 0; off >>= 1)
                sgn += __shfl_xor_sync(0xffffffffu, sgn, off);
            if (lane == 0) g_z[b * 4 + w] = sgn;
        }
    }
}

// ------------------------- K2: BN stats + fold into coefficients -----------
__global__ void k_reduce(const float* __restrict__ gam, const float* __restrict__ bet,
                         const float* __restrict__ fcw, const float* __restrict__ fcb,
                         int B) {
    __shared__ double red[256 * 8];
    int tid = threadIdx.x;
    double sm[4] = {0, 0, 0, 0}, sq[4] = {0, 0, 0, 0};
    for (int r = tid; r < B; r += 256) {
#pragma unroll
        for (int j = 0; j < 4; j++) {
            double v = (double)g_z[r * 4 + j];
            sm[j] += v;
            sq[j] += v * v;
        }
    }
#pragma unroll
    for (int j = 0; j < 4; j++) { red[tid * 8 + j] = sm[j]; red[tid * 8 + 4 + j] = sq[j]; }
    __syncthreads();
    for (int s = 128; s > 0; s >>= 1) {
        if (tid < s) {
#pragma unroll
            for (int j = 0; j < 8; j++) red[tid * 8 + j] += red[(tid + s) * 8 + j];
        }
        __syncthreads();
    }
    if (tid == 0) {
        double invB = 1.0 / (double)B;
        double csum = (double)fcb[0];
        for (int j = 0; j < 4; j++) {
            double mu = red[j] * invB;
            double var = red[4 + j] * invB - mu * mu;
            double sc = (double)gam[j] / sqrt(var + 1e-5);
            g_coef[j] = (float)((double)fcw[j] * sc);
            csum += (double)fcw[j] * ((double)bet[j] - mu * sc);
        }
        g_coef[4] = (float)csum;
    }
}

// ------------------------- K3: final output --------------------------------
__global__ void k_final(float* __restrict__ out, int B) {
    int b = blockIdx.x * blockDim.x + threadIdx.x;
    if (b < B) {
        out[b] = g_coef[4]
               + g_coef[0] * g_z[b * 4 + 0]
               + g_coef[1] * g_z[b * 4 + 1]
               + g_coef[2] * g_z[b * 4 + 2]
               + g_coef[3] * g_z[b * 4 + 3];
    }
}

extern "C" void kernel_launch(void* const* d_in, const int* in_sizes, int n_in,
                              void* d_out, int out_size) {
    const float* x   = (const float*)d_in[0];
    const float* c1w = (const float*)d_in[1];
    const float* c1b = (const float*)d_in[2];
    const float* c2w = (const float*)d_in[3];
    const float* c2b = (const float*)d_in[4];
    const float* gp  = (const float*)d_in[5];
    const float* rp  = (const float*)d_in[6];
    const float* gam = (const float*)d_in[7];
    const float* bet = (const float*)d_in[8];
    const float* fcw = (const float*)d_in[9];
    const float* fcb = (const float*)d_in[10];

    int B = in_sizes[0] / 784;
    if (B > BMAX) B = BMAX;

    k_setup<<<1, 32>>>(gp, rp);
    k_main<<<B, 128>>>(x, c1w, c1b, c2w, c2b);
    k_reduce<<<1, 256>>>(gam, bet, fcw, fcb, B);
    k_final<<<(B + 255) / 256, 256>>>((float*)d_out, B);
}

// round 9
// speedup vs baseline: 1.0781x; 1.0072x over previous
#include <cuda_runtime.h>
#include <math.h>

// ---------------------------------------------------------------------------
// FraudNATHybridModel — R9: R4 inner loops (best so far) + 2 images per
// 224-thread block (100% warp utilization, staging amortized) + k_final
// merged into k_reduce.
// ---------------------------------------------------------------------------

#define BMAX 8192

__device__ float2 g_U[256];
__device__ float  g_z[BMAX * 4];

#define PACK2(out, lo, hi) \
    asm("mov.b64 %0, {%1, %2};" : "=l"(out) : "r"(__float_as_uint(lo)), "r"(__float_as_uint(hi)))
#define UNPACK2(lo, hi, in) \
    do { unsigned _ulo, _uhi; \
         asm("mov.b64 {%0, %1}, %2;" : "=r"(_ulo), "=r"(_uhi) : "l"(in)); \
         lo = __uint_as_float(_ulo); hi = __uint_as_float(_uhi); } while (0)
#define FMA2(acc, a, b) \
    asm("fma.rn.f32x2 %0, %1, %2, %0;" : "+l"(acc) : "l"(a), "l"(b))

__device__ __forceinline__ float2 cmul(float2 a, float2 b) {
    return make_float2(a.x * b.x - a.y * b.y, a.x * b.y + a.y * b.x);
}
__device__ __forceinline__ float2 cadd(float2 a, float2 b) {
    return make_float2(a.x + b.x, a.y + b.y);
}
__device__ __forceinline__ float2 cfma_(float2 a, float2 b, float2 c) {
    c.x += a.x * b.x - a.y * b.y;
    c.y += a.x * b.y + a.y * b.x;
    return c;
}

// ------------------------- MT19937 (numpy legacy) --------------------------
__device__ unsigned mt_next(unsigned* mt, int* mti) {
    if (*mti >= 624) {
        for (int i = 0; i < 624; i++) {
            unsigned y = (mt[i] & 0x80000000u) | (mt[(i + 1) % 624] & 0x7fffffffu);
            unsigned v = mt[(i + 397) % 624] ^ (y >> 1);
            if (y & 1u) v ^= 0x9908b0dfu;
            mt[i] = v;
        }
        *mti = 0;
    }
    unsigned y = mt[(*mti)++];
    y ^= y >> 11;
    y ^= (y << 7) & 0x9d2c5680u;
    y ^= (y << 15) & 0xefc60000u;
    y ^= y >> 18;
    return y;
}

__device__ void ap1(float2* s, int w, float2 u00, float2 u01, float2 u10, float2 u11) {
    int m = 8 >> w;
    for (int i = 0; i < 16; i++) {
        if (!(i & m)) {
            float2 a = s[i], b = s[i | m];
            s[i]     = cadd(cmul(u00, a), cmul(u01, b));
            s[i | m] = cadd(cmul(u10, a), cmul(u11, b));
        }
    }
}
__device__ void ap2(float2* s, int wc, int wt, float2 u00, float2 u01, float2 u10, float2 u11) {
    int mc = 8 >> wc, mt2 = 8 >> wt;
    for (int i = 0; i < 16; i++) {
        if ((i & mc) && !(i & mt2)) {
            float2 a = s[i], b = s[i | mt2];
            s[i]       = cadd(cmul(u00, a), cmul(u01, b));
            s[i | mt2] = cadd(cmul(u10, a), cmul(u11, b));
        }
    }
}

// ------------------------- K0: build U_post --------------------------------
__global__ void k_setup(const float* __restrict__ gate_params,
                        const float* __restrict__ rand_params) {
    __shared__ unsigned smt[624];
    __shared__ int sg[50], sw0[50], sw1[50], sp[50];
    int tid = threadIdx.x;

    if (tid == 0) {
        smt[0] = 12345u;
        for (int i = 1; i < 624; i++)
            smt[i] = 1812433253u * (smt[i - 1] ^ (smt[i - 1] >> 30)) + (unsigned)i;
        int mti = 624;
        int p = 0;
        for (int k = 0; k < 50; k++) {
            unsigned g;
            do { g = mt_next(smt, &mti) & 7u; } while (g > 4u);
            int w0, w1 = -1;
            if (g >= 3u) {
                int arr[4] = {0, 1, 2, 3};
                for (int i = 3; i >= 1; --i) {
                    unsigned mask = (unsigned)i;
                    mask |= mask >> 1; mask |= mask >> 2; mask |= mask >> 4;
                    unsigned j;
                    do { j = mt_next(smt, &mti) & mask; } while (j > (unsigned)i);
                    int t = arr[i]; arr[i] = arr[j]; arr[j] = t;
                }
                w0 = arr[0]; w1 = arr[1];
            } else {
                w0 = (int)(mt_next(smt, &mti) & 3u);
            }
            sg[k] = (int)g; sw0[k] = w0; sw1[k] = w1;
            sp[k] = (g == 4u) ? -1 : p++;
        }
    }
    __syncthreads();

    if (tid < 16) {
        float2 st[16];
        for (int i = 0; i < 16; i++) st[i] = make_float2(i == tid ? 1.f : 0.f, 0.f);

        for (int k = 0; k < 50; k++) {
            int g = sg[k], w0 = sw0[k], w1 = sw1[k];
            float t = (sp[k] >= 0) ? rand_params[sp[k]] : 0.f;
            float sn, cs;
            sincosf(0.5f * t, &sn, &cs);
            if (g == 0) {
                ap1(st, w0, make_float2(cs, 0), make_float2(0, -sn),
                            make_float2(0, -sn), make_float2(cs, 0));
            } else if (g == 1) {
                ap1(st, w0, make_float2(cs, 0), make_float2(-sn, 0),
                            make_float2(sn, 0), make_float2(cs, 0));
            } else if (g == 2) {
                ap1(st, w0, make_float2(cs, -sn), make_float2(0, 0),
                            make_float2(0, 0), make_float2(cs, sn));
            } else if (g == 3) {
                ap2(st, w0, w1, make_float2(cs, 0), make_float2(0, -sn),
                                make_float2(0, -sn), make_float2(cs, 0));
            } else {
                ap2(st, w0, w1, make_float2(0, 0), make_float2(1, 0),
                                make_float2(1, 0), make_float2(0, 0));
            }
        }
        float sn, cs;
        sincosf(0.5f * gate_params[0], &sn, &cs);
        ap1(st, 0, make_float2(cs, 0), make_float2(0, -sn), make_float2(0, -sn), make_float2(cs, 0));
        sincosf(0.5f * gate_params[1], &sn, &cs);
        ap1(st, 1, make_float2(cs, 0), make_float2(-sn, 0), make_float2(sn, 0), make_float2(cs, 0));
        sincosf(0.5f * gate_params[2], &sn, &cs);
        ap1(st, 3, make_float2(cs, -sn), make_float2(0, 0), make_float2(0, 0), make_float2(cs, sn));
        sincosf(0.5f * gate_params[3], &sn, &cs);
        ap2(st, 0, 2, make_float2(cs, 0), make_float2(0, -sn), make_float2(0, -sn), make_float2(cs, 0));
        const float r = 0.70710678118654752f;
        ap1(st, 3, make_float2(r, 0), make_float2(r, 0), make_float2(r, 0), make_float2(-r, 0));
        ap1(st, 2, make_float2(0.5f, 0.5f), make_float2(0.5f, -0.5f),
                   make_float2(0.5f, -0.5f), make_float2(0.5f, 0.5f));
        ap2(st, 3, 0, make_float2(0, 0), make_float2(1, 0), make_float2(1, 0), make_float2(0, 0));

        for (int i = 0; i < 16; i++) g_U[i * 16 + tid] = st[i];
    }
}

// ------------------------- K1: fused pipeline, 2 images / block ------------
__global__ __launch_bounds__(224) void k_main(const float* __restrict__ x,
                                              const float* __restrict__ w1,
                                              const float* __restrict__ b1,
                                              const float* __restrict__ w2,
                                              const float* __restrict__ b2,
                                              int B) {
    __shared__ float sx[2][28 * 29];       // row stride 29 -> conflict-free
    __shared__ float sw1c[72];
    __shared__ float sb1[8];
    __shared__ float sh1[2][8 * 196];      // conv1 pooled [8][14][14]
    __shared__ __align__(16) float sw2c2[1152];  // conv2 weights [k][oc]
    __shared__ float sb2[16];
    __shared__ float shm[2][16 * 14 * 7];  // conv2 horizontally-pooled rows
    __shared__ float spart[2][112];
    __shared__ float spool[2][16];
    __shared__ float2 sv[2][8];
    __shared__ float2 sphi[2][16];

    int tid = threadIdx.x;
    int img = tid / 112;                   // 0 or 1
    int t   = tid - img * 112;             // 0..111
    int bimg = 2 * blockIdx.x + img;
    bool act = bimg < B;

    // ---- stage weights (whole block) ----
    for (int i = tid; i < 72; i += 224) sw1c[i] = w1[i];
    if (tid < 8) sb1[tid] = b1[tid];
    for (int i = tid; i < 1152; i += 224) {
        int k = i >> 4, oc = i & 15;
        sw2c2[i] = w2[oc * 72 + k];        // transpose to [k][oc]
    }
    if (tid < 16) sb2[tid] = b2[tid];
    // ---- stage this group's image ----
    if (act) {
        const float* xb = x + (size_t)bimg * 784;
        for (int i = t; i < 784; i += 112) {
            int r = i / 28, c = i % 28;
            sx[img][r * 29 + c] = xb[i];
        }
    }
    __syncthreads();

    // ---- conv1 (1->8, 3x3 SAME) + relu + maxpool2 -> sh1 ----
    {
        int c = t / 14, y = t % 14;
        float om[14];
#pragma unroll
        for (int i = 0; i < 14; i++) om[i] = 0.f;   // relu >= 0
        float bias = sb1[c];
#pragma unroll
        for (int dy = 0; dy < 2; dy++) {
            int rrow = 2 * y + dy;
            float cr[28];
#pragma unroll
            for (int i = 0; i < 28; i++) cr[i] = bias;
#pragma unroll
            for (int ky = 0; ky < 3; ky++) {
                int iy = rrow + ky - 1;
                if (iy >= 0 && iy < 28) {
                    float rb[30];
                    rb[0] = 0.f; rb[29] = 0.f;
#pragma unroll
                    for (int i = 0; i < 28; i++) rb[i + 1] = sx[img][iy * 29 + i];
#pragma unroll
                    for (int kx = 0; kx < 3; kx++) {
                        float w = sw1c[c * 9 + ky * 3 + kx];
#pragma unroll
                        for (int i = 0; i < 28; i++) cr[i] += w * rb[i + kx];
                    }
                }
            }
#pragma unroll
            for (int i = 0; i < 14; i++)
                om[i] = fmaxf(om[i], fmaxf(cr[2 * i], cr[2 * i + 1]));
        }
#pragma unroll
        for (int i = 0; i < 14; i++) sh1[img][(c * 14 + y) * 14 + i] = om[i];
    }
    __syncthreads();

    // ---- conv2 (8->16) packed f32x2 over channel pairs + horiz pooling ----
    {
        int cp = t / 14, y = t % 14;
        unsigned long long acc[14];
        {
            unsigned long long bias2;
            PACK2(bias2, sb2[2 * cp], sb2[2 * cp + 1]);
#pragma unroll
            for (int i = 0; i < 14; i++) acc[i] = bias2;
        }
#pragma unroll
        for (int ic = 0; ic < 8; ic++) {
#pragma unroll
            for (int ky = 0; ky < 3; ky++) {
                int iy = y + ky - 1;
                if (iy >= 0 && iy < 14) {
                    unsigned long long rp[16];
                    rp[0] = 0ull; rp[15] = 0ull;
#pragma unroll
                    for (int i = 0; i < 14; i++) {
                        float v = sh1[img][(ic * 14 + iy) * 14 + i];
                        PACK2(rp[i + 1], v, v);
                    }
#pragma unroll
                    for (int kx = 0; kx < 3; kx++) {
                        float2 wf = *(const float2*)&sw2c2[((ic * 3 + ky) * 3 + kx) * 16 + 2 * cp];
                        unsigned long long w2p;
                        PACK2(w2p, wf.x, wf.y);
#pragma unroll
                        for (int i = 0; i < 14; i++)
                            FMA2(acc[i], w2p, rp[i + kx]);
                    }
                }
            }
        }
        // unpack + horizontal max of adjacent pairs (relu deferred)
#pragma unroll
        for (int i = 0; i < 7; i++) {
            float a0l, a1l, a0h, a1h;
            UNPACK2(a0l, a1l, acc[2 * i]);
            UNPACK2(a0h, a1h, acc[2 * i + 1]);
            shm[img][((2 * cp) * 14 + y) * 7 + i]     = fmaxf(a0l, a0h);
            shm[img][((2 * cp + 1) * 14 + y) * 7 + i] = fmaxf(a1l, a1h);
        }
    }
    __syncthreads();

    // ---- vertical max of row pairs + relu + row sum -> spart ----
    {
        int c = t / 7, y2 = t % 7;
        const float* r0 = &shm[img][(c * 14 + 2 * y2) * 7];
        const float* r1 = r0 + 7;
        float psum = 0.f;
#pragma unroll
        for (int i = 0; i < 7; i++)
            psum += fmaxf(fmaxf(r0[i], r1[i]), 0.f);
        spart[img][c * 7 + y2] = psum;
    }
    __syncthreads();

    if (t < 16) {
        float s = 0.f;
#pragma unroll
        for (int j = 0; j < 7; j++) s += spart[img][t * 7 + j];
        spool[img][t] = s * (1.f / 49.f);
    }
    __syncthreads();

    // ---- quantum: warp 0 handles img 0, warp 4 handles img 1 ----
    {
        int w = tid >> 5;
        int qimg = (w == 0) ? 0 : ((w == 4) ? 1 : -1);
        if (qimg >= 0) {
            int lane = tid & 31;
            int qb = 2 * blockIdx.x + qimg;
            if (lane < 4) {
                float aa = spool[qimg][lane], bb = spool[qimg][4 + lane],
                      cc = spool[qimg][8 + lane], dd = spool[qimg][12 + lane];
                float sa, ca, sb, cb, sc, ccs, sd, cd;
                sincosf(0.5f * aa, &sa, &ca);
                sincosf(0.5f * bb, &sb, &cb);
                sincosf(0.5f * cc, &sc, &ccs);
                sincosf(0.5f * dd, &sd, &cd);
                float2 v0 = make_float2(ca * cb, -ca * sb);
                float2 v1 = make_float2(sa * cb, sa * sb);
                float2 t0 = make_float2(ccs * v0.x + sc * v1.y, ccs * v0.y - sc * v1.x);
                float2 t1 = make_float2(sc * v0.y + ccs * v1.x, -sc * v0.x + ccs * v1.y);
                float2 u0 = make_float2(cd * t0.x - sd * t1.x, cd * t0.y - sd * t1.y);
                float2 u1 = make_float2(sd * t0.x + cd * t1.x, sd * t0.y + cd * t1.y);
                sv[qimg][2 * lane] = u0;
                sv[qimg][2 * lane + 1] = u1;
            }
            __syncwarp();
            if (lane < 16) {
                float2 f0 = sv[qimg][0 + ((lane >> 3) & 1)];
                float2 f1 = sv[qimg][2 + ((lane >> 2) & 1)];
                float2 f2 = sv[qimg][4 + ((lane >> 1) & 1)];
                float2 f3 = sv[qimg][6 + (lane & 1)];
                sphi[qimg][lane] = cmul(cmul(f0, f1), cmul(f2, f3));
            }
            __syncwarp();
            float p = 0.f;
            if (lane < 16) {
                float2 psi = make_float2(0.f, 0.f);
#pragma unroll
                for (int j = 0; j < 16; j++) psi = cfma_(g_U[lane * 16 + j], sphi[qimg][j], psi);
                p = psi.x * psi.x + psi.y * psi.y;
            }
#pragma unroll
            for (int wq = 0; wq < 4; wq++) {
                float sgn = ((lane >> (3 - wq)) & 1) ? -p : p;
#pragma unroll
                for (int off = 16; off > 0; off >>= 1)
                    sgn += __shfl_xor_sync(0xffffffffu, sgn, off);
                if (lane == 0 && qb < B) g_z[qb * 4 + wq] = sgn;
            }
        }
    }
}

// --------------- K2: BN stats + fold + write outputs (merged) --------------
__global__ void k_reduce(const float* __restrict__ gam, const float* __restrict__ bet,
                         const float* __restrict__ fcw, const float* __restrict__ fcb,
                         float* __restrict__ out, int B) {
    __shared__ double red[256 * 8];
    __shared__ float scoef[5];
    int tid = threadIdx.x;
    double sm[4] = {0, 0, 0, 0}, sq[4] = {0, 0, 0, 0};
    for (int r = tid; r < B; r += 256) {
#pragma unroll
        for (int j = 0; j < 4; j++) {
            double v = (double)g_z[r * 4 + j];
            sm[j] += v;
            sq[j] += v * v;
        }
    }
#pragma unroll
    for (int j = 0; j < 4; j++) { red[tid * 8 + j] = sm[j]; red[tid * 8 + 4 + j] = sq[j]; }
    __syncthreads();
    for (int s = 128; s > 0; s >>= 1) {
        if (tid < s) {
#pragma unroll
            for (int j = 0; j < 8; j++) red[tid * 8 + j] += red[(tid + s) * 8 + j];
        }
        __syncthreads();
    }
    if (tid == 0) {
        double invB = 1.0 / (double)B;
        double csum = (double)fcb[0];
        for (int j = 0; j < 4; j++) {
            double mu = red[j] * invB;
            double var = red[4 + j] * invB - mu * mu;
            double sc = (double)gam[j] / sqrt(var + 1e-5);
            scoef[j] = (float)((double)fcw[j] * sc);
            csum += (double)fcw[j] * ((double)bet[j] - mu * sc);
        }
        scoef[4] = (float)csum;
    }
    __syncthreads();
    float c0 = scoef[0], c1 = scoef[1], c2 = scoef[2], c3 = scoef[3], c4 = scoef[4];
    for (int b = tid; b < B; b += 256) {
        out[b] = c4 + c0 * g_z[b * 4 + 0] + c1 * g_z[b * 4 + 1]
                    + c2 * g_z[b * 4 + 2] + c3 * g_z[b * 4 + 3];
    }
}

extern "C" void kernel_launch(void* const* d_in, const int* in_sizes, int n_in,
                              void* d_out, int out_size) {
    const float* x   = (const float*)d_in[0];
    const float* c1w = (const float*)d_in[1];
    const float* c1b = (const float*)d_in[2];
    const float* c2w = (const float*)d_in[3];
    const float* c2b = (const float*)d_in[4];
    const float* gp  = (const float*)d_in[5];
    const float* rp  = (const float*)d_in[6];
    const float* gam = (const float*)d_in[7];
    const float* bet = (const float*)d_in[8];
    const float* fcw = (const float*)d_in[9];
    const float* fcb = (const float*)d_in[10];

    int B = in_sizes[0] / 784;
    if (B > BMAX) B = BMAX;

    k_setup<<<1, 32>>>(gp, rp);
    k_main<<<(B + 1) / 2, 224>>>(x, c1w, c1b, c2w, c2b, B);
    k_reduce<<<1, 256>>>(gam, bet, fcw, fcb, (float*)d_out, B);
}

// round 10
// speedup vs baseline: 1.3262x; 1.2301x over previous
#include <cuda_runtime.h>
#include <math.h>
#include <string.h>

// ---------------------------------------------------------------------------
// FraudNATHybridModel — R10: R4 k_main (best known) + host-side MT19937 spec
// generation (deterministic seed 12345 -> constant) passed as kernel struct
// param + fast smem-state k_setup (~3us vs 63us) + merged reduce/output.
// ---------------------------------------------------------------------------

#define BMAX 8192
#define NGATES 57

struct GateSpec {
    int g[NGATES];    // 0 rx, 1 ry, 2 rz, 3 crx, 4 cnot, 5 H, 6 SX
    int w0[NGATES];
    int w1[NGATES];
    int pi[NGATES];   // >=0: rand_params[pi]; -2-j: gate_params[j]; -1: none
};

__device__ float2 g_U[256];
__device__ float  g_z[BMAX * 4];

#define PACK2(out, lo, hi) \
    asm("mov.b64 %0, {%1, %2};" : "=l"(out) : "r"(__float_as_uint(lo)), "r"(__float_as_uint(hi)))
#define UNPACK2(lo, hi, in) \
    do { unsigned _ulo, _uhi; \
         asm("mov.b64 {%0, %1}, %2;" : "=r"(_ulo), "=r"(_uhi) : "l"(in)); \
         lo = __uint_as_float(_ulo); hi = __uint_as_float(_uhi); } while (0)
#define FMA2(acc, a, b) \
    asm("fma.rn.f32x2 %0, %1, %2, %0;" : "+l"(acc) : "l"(a), "l"(b))

__device__ __forceinline__ float2 cmul(float2 a, float2 b) {
    return make_float2(a.x * b.x - a.y * b.y, a.x * b.y + a.y * b.x);
}
__device__ __forceinline__ float2 cadd(float2 a, float2 b) {
    return make_float2(a.x + b.x, a.y + b.y);
}
__device__ __forceinline__ float2 cfma_(float2 a, float2 b, float2 c) {
    c.x += a.x * b.x - a.y * b.y;
    c.y += a.x * b.y + a.y * b.x;
    return c;
}

// ------------------------- K0: build U_post (fast) -------------------------
__global__ void k_setup(const float* __restrict__ gate_params,
                        const float* __restrict__ rand_params,
                        GateSpec spec) {
    __shared__ float2 smat[NGATES][4];     // u00,u01,u10,u11
    __shared__ float2 sst[16][17];         // [state][column], padded
    int tid = threadIdx.x;

    if (tid < NGATES) {
        int g = spec.g[tid];
        int pi = spec.pi[tid];
        float t = 0.f;
        if (pi >= 0) t = rand_params[pi];
        else if (pi <= -2) t = gate_params[-2 - pi];
        float sn, cs;
        sincosf(0.5f * t, &sn, &cs);
        float2 u00, u01, u10, u11;
        if (g == 0 || g == 3) {            // rx / crx
            u00 = make_float2(cs, 0.f);  u01 = make_float2(0.f, -sn);
            u10 = make_float2(0.f, -sn); u11 = make_float2(cs, 0.f);
        } else if (g == 1) {               // ry
            u00 = make_float2(cs, 0.f);  u01 = make_float2(-sn, 0.f);
            u10 = make_float2(sn, 0.f);  u11 = make_float2(cs, 0.f);
        } else if (g == 2) {               // rz
            u00 = make_float2(cs, -sn);  u01 = make_float2(0.f, 0.f);
            u10 = make_float2(0.f, 0.f); u11 = make_float2(cs, sn);
        } else if (g == 4) {               // cnot
            u00 = make_float2(0.f, 0.f); u01 = make_float2(1.f, 0.f);
            u10 = make_float2(1.f, 0.f); u11 = make_float2(0.f, 0.f);
        } else if (g == 5) {               // H
            const float r = 0.70710678118654752f;
            u00 = make_float2(r, 0.f);   u01 = make_float2(r, 0.f);
            u10 = make_float2(r, 0.f);   u11 = make_float2(-r, 0.f);
        } else {                           // SX
            u00 = make_float2(0.5f, 0.5f);  u01 = make_float2(0.5f, -0.5f);
            u10 = make_float2(0.5f, -0.5f); u11 = make_float2(0.5f, 0.5f);
        }
        smat[tid][0] = u00; smat[tid][1] = u01;
        smat[tid][2] = u10; smat[tid][3] = u11;
    }
    __syncthreads();

    if (tid < 16) {
        // column tid of U: start from basis state |tid>
        for (int i = 0; i < 16; i++)
            sst[i][tid] = make_float2(i == tid ? 1.f : 0.f, 0.f);

        for (int k = 0; k < NGATES; k++) {
            int g = spec.g[k];
            float2 u00 = smat[k][0], u01 = smat[k][1];
            float2 u10 = smat[k][2], u11 = smat[k][3];
            if (g == 3 || g == 4) {
                int mc = 8 >> spec.w0[k], mt = 8 >> spec.w1[k];
                for (int i = 0; i < 16; i++) {
                    if ((i & mc) && !(i & mt)) {
                        float2 a = sst[i][tid], b = sst[i | mt][tid];
                        sst[i][tid]      = cadd(cmul(u00, a), cmul(u01, b));
                        sst[i | mt][tid] = cadd(cmul(u10, a), cmul(u11, b));
                    }
                }
            } else {
                int m = 8 >> spec.w0[k];
                for (int i = 0; i < 16; i++) {
                    if (!(i & m)) {
                        float2 a = sst[i][tid], b = sst[i | m][tid];
                        sst[i][tid]     = cadd(cmul(u00, a), cmul(u01, b));
                        sst[i | m][tid] = cadd(cmul(u10, a), cmul(u11, b));
                    }
                }
            }
        }
        for (int i = 0; i < 16; i++) g_U[i * 16 + tid] = sst[i][tid];
    }
}

// ------------------------- K1: fused per-image pipeline (R4 verbatim) ------
__global__ __launch_bounds__(128) void k_main(const float* __restrict__ x,
                                              const float* __restrict__ w1,
                                              const float* __restrict__ b1,
                                              const float* __restrict__ w2,
                                              const float* __restrict__ b2) {
    __shared__ float sx[28 * 29];        // row stride 29 -> conflict-free
    __shared__ float sw1c[72];
    __shared__ float sb1[8];
    __shared__ float sh1[8 * 196];       // conv1 pooled output [8][14][14]
    __shared__ __align__(16) float sw2c2[1152];  // conv2 weights [k][oc]
    __shared__ float sb2[16];
    __shared__ float shm[16 * 14 * 7];   // conv2 horizontally-pooled rows
    __shared__ float spart[112];
    __shared__ float spool[16];
    __shared__ float2 sv[8];
    __shared__ float2 sphi[16];

    int tid = threadIdx.x;
    int b = blockIdx.x;
    const float* xb = x + (size_t)b * 784;

    for (int i = tid; i < 784; i += 128) {
        int r = i / 28, c = i % 28;
        sx[r * 29 + c] = xb[i];
    }
    for (int i = tid; i < 72; i += 128) sw1c[i] = w1[i];
    if (tid < 8) sb1[tid] = b1[tid];
    for (int i = tid; i < 1152; i += 128) {
        int k = i >> 4, oc = i & 15;
        sw2c2[i] = w2[oc * 72 + k];      // transpose to [k][oc]
    }
    if (tid < 16) sb2[tid] = b2[tid];
    __syncthreads();

    // ---- conv1 (1->8, 3x3 SAME) + relu + maxpool2 -> sh1 ----
    if (tid < 112) {
        int c = tid / 14, y = tid % 14;
        float om[14];
#pragma unroll
        for (int i = 0; i < 14; i++) om[i] = 0.f;   // relu >= 0
        float bias = sb1[c];
#pragma unroll
        for (int dy = 0; dy < 2; dy++) {
            int rrow = 2 * y + dy;
            float cr[28];
#pragma unroll
            for (int i = 0; i < 28; i++) cr[i] = bias;
#pragma unroll
            for (int ky = 0; ky < 3; ky++) {
                int iy = rrow + ky - 1;
                if (iy >= 0 && iy < 28) {
                    float rb[30];
                    rb[0] = 0.f; rb[29] = 0.f;
#pragma unroll
                    for (int i = 0; i < 28; i++) rb[i + 1] = sx[iy * 29 + i];
#pragma unroll
                    for (int kx = 0; kx < 3; kx++) {
                        float w = sw1c[c * 9 + ky * 3 + kx];
#pragma unroll
                        for (int i = 0; i < 28; i++) cr[i] += w * rb[i + kx];
                    }
                }
            }
#pragma unroll
            for (int i = 0; i < 14; i++)
                om[i] = fmaxf(om[i], fmaxf(cr[2 * i], cr[2 * i + 1]));
        }
#pragma unroll
        for (int i = 0; i < 14; i++) sh1[(c * 14 + y) * 14 + i] = om[i];
    }
    __syncthreads();

    // ---- conv2 (8->16) packed f32x2 over channel pairs + horiz pooling ----
    if (tid < 112) {
        int cp = tid / 14, y = tid % 14;
        unsigned long long acc[14];
        {
            unsigned long long bias2;
            PACK2(bias2, sb2[2 * cp], sb2[2 * cp + 1]);
#pragma unroll
            for (int i = 0; i < 14; i++) acc[i] = bias2;
        }
#pragma unroll
        for (int ic = 0; ic < 8; ic++) {
#pragma unroll
            for (int ky = 0; ky < 3; ky++) {
                int iy = y + ky - 1;
                if (iy >= 0 && iy < 14) {
                    unsigned long long rp[16];
                    rp[0] = 0ull; rp[15] = 0ull;
#pragma unroll
                    for (int i = 0; i < 14; i++) {
                        float v = sh1[(ic * 14 + iy) * 14 + i];
                        PACK2(rp[i + 1], v, v);
                    }
#pragma unroll
                    for (int kx = 0; kx < 3; kx++) {
                        float2 wf = *(const float2*)&sw2c2[((ic * 3 + ky) * 3 + kx) * 16 + 2 * cp];
                        unsigned long long w2p;
                        PACK2(w2p, wf.x, wf.y);
#pragma unroll
                        for (int i = 0; i < 14; i++)
                            FMA2(acc[i], w2p, rp[i + kx]);
                    }
                }
            }
        }
        // unpack + horizontal max of adjacent pairs (relu deferred)
#pragma unroll
        for (int i = 0; i < 7; i++) {
            float a0l, a1l, a0h, a1h;
            UNPACK2(a0l, a1l, acc[2 * i]);
            UNPACK2(a0h, a1h, acc[2 * i + 1]);
            shm[((2 * cp) * 14 + y) * 7 + i]     = fmaxf(a0l, a0h);
            shm[((2 * cp + 1) * 14 + y) * 7 + i] = fmaxf(a1l, a1h);
        }
    }
    __syncthreads();

    // ---- vertical max of row pairs + relu + row sum -> spart ----
    if (tid < 112) {
        int c = tid / 7, y2 = tid % 7;
        const float* r0 = &shm[(c * 14 + 2 * y2) * 7];
        const float* r1 = r0 + 7;
        float psum = 0.f;
#pragma unroll
        for (int i = 0; i < 7; i++)
            psum += fmaxf(fmaxf(r0[i], r1[i]), 0.f);
        spart[c * 7 + y2] = psum;
    }
    __syncthreads();

    if (tid < 16) {
        float s = 0.f;
#pragma unroll
        for (int j = 0; j < 7; j++) s += spart[tid * 7 + j];
        spool[tid] = s * (1.f / 49.f);
    }
    __syncthreads();

    // ---- quantum: product-state encoder, psi = U_post * phi, Z expectations
    if (tid < 32) {
        int lane = tid;
        if (lane < 4) {
            float aa = spool[lane], bb = spool[4 + lane],
                  cc = spool[8 + lane], dd = spool[12 + lane];
            float sa, ca, sb, cb, sc, ccs, sd, cd;
            sincosf(0.5f * aa, &sa, &ca);
            sincosf(0.5f * bb, &sb, &cb);
            sincosf(0.5f * cc, &sc, &ccs);
            sincosf(0.5f * dd, &sd, &cd);
            float2 v0 = make_float2(ca * cb, -ca * sb);
            float2 v1 = make_float2(sa * cb, sa * sb);
            float2 t0 = make_float2(ccs * v0.x + sc * v1.y, ccs * v0.y - sc * v1.x);
            float2 t1 = make_float2(sc * v0.y + ccs * v1.x, -sc * v0.x + ccs * v1.y);
            float2 u0 = make_float2(cd * t0.x - sd * t1.x, cd * t0.y - sd * t1.y);
            float2 u1 = make_float2(sd * t0.x + cd * t1.x, sd * t0.y + cd * t1.y);
            sv[2 * lane] = u0;
            sv[2 * lane + 1] = u1;
        }
        __syncwarp();
        if (lane < 16) {
            float2 f0 = sv[0 + ((lane >> 3) & 1)];
            float2 f1 = sv[2 + ((lane >> 2) & 1)];
            float2 f2 = sv[4 + ((lane >> 1) & 1)];
            float2 f3 = sv[6 + (lane & 1)];
            sphi[lane] = cmul(cmul(f0, f1), cmul(f2, f3));
        }
        __syncwarp();
        float p = 0.f;
        if (lane < 16) {
            float2 psi = make_float2(0.f, 0.f);
#pragma unroll
            for (int j = 0; j < 16; j++) psi = cfma_(g_U[lane * 16 + j], sphi[j], psi);
            p = psi.x * psi.x + psi.y * psi.y;
        }
#pragma unroll
        for (int w = 0; w < 4; w++) {
            float sgn = ((lane >> (3 - w)) & 1) ? -p : p;
#pragma unroll
            for (int off = 16; off > 0; off >>= 1)
                sgn += __shfl_xor_sync(0xffffffffu, sgn, off);
            if (lane == 0) g_z[b * 4 + w] = sgn;
        }
    }
}

// --------------- K2: BN stats + fold + write outputs (merged) --------------
__global__ void k_reduce(const float* __restrict__ gam, const float* __restrict__ bet,
                         const float* __restrict__ fcw, const float* __restrict__ fcb,
                         float* __restrict__ out, int B) {
    __shared__ double red[256 * 8];
    __shared__ float scoef[5];
    int tid = threadIdx.x;
    double sm[4] = {0, 0, 0, 0}, sq[4] = {0, 0, 0, 0};
    for (int r = tid; r < B; r += 256) {
#pragma unroll
        for (int j = 0; j < 4; j++) {
            double v = (double)g_z[r * 4 + j];
            sm[j] += v;
            sq[j] += v * v;
        }
    }
#pragma unroll
    for (int j = 0; j < 4; j++) { red[tid * 8 + j] = sm[j]; red[tid * 8 + 4 + j] = sq[j]; }
    __syncthreads();
    for (int s = 128; s > 0; s >>= 1) {
        if (tid < s) {
#pragma unroll
            for (int j = 0; j < 8; j++) red[tid * 8 + j] += red[(tid + s) * 8 + j];
        }
        __syncthreads();
    }
    if (tid == 0) {
        double invB = 1.0 / (double)B;
        double csum = (double)fcb[0];
        for (int j = 0; j < 4; j++) {
            double mu = red[j] * invB;
            double var = red[4 + j] * invB - mu * mu;
            double sc = (double)gam[j] / sqrt(var + 1e-5);
            scoef[j] = (float)((double)fcw[j] * sc);
            csum += (double)fcw[j] * ((double)bet[j] - mu * sc);
        }
        scoef[4] = (float)csum;
    }
    __syncthreads();
    float c0 = scoef[0], c1 = scoef[1], c2 = scoef[2], c3 = scoef[3], c4 = scoef[4];
    for (int b = tid; b < B; b += 256) {
        out[b] = c4 + c0 * g_z[b * 4 + 0] + c1 * g_z[b * 4 + 1]
                    + c2 * g_z[b * 4 + 2] + c3 * g_z[b * 4 + 3];
    }
}

// ------------------- host-side MT19937 spec generation ---------------------
// Verbatim port of the (correctness-verified) device implementation.
static unsigned host_mt_next(unsigned* mt, int* mti) {
    if (*mti >= 624) {
        for (int i = 0; i < 624; i++) {
            unsigned y = (mt[i] & 0x80000000u) | (mt[(i + 1) % 624] & 0x7fffffffu);
            unsigned v = mt[(i + 397) % 624] ^ (y >> 1);
            if (y & 1u) v ^= 0x9908b0dfu;
            mt[i] = v;
        }
        *mti = 0;
    }
    unsigned y = mt[(*mti)++];
    y ^= y >> 11;
    y ^= (y << 7) & 0x9d2c5680u;
    y ^= (y << 15) & 0xefc60000u;
    y ^= y >> 18;
    return y;
}

static void host_build_spec(GateSpec* s) {
    unsigned mt[624];
    mt[0] = 12345u;
    for (int i = 1; i < 624; i++)
        mt[i] = 1812433253u * (mt[i - 1] ^ (mt[i - 1] >> 30)) + (unsigned)i;
    int mti = 624;
    int p = 0;
    for (int k = 0; k < 50; k++) {
        unsigned g;
        do { g = host_mt_next(mt, &mti) & 7u; } while (g > 4u);
        int w0, w1 = -1;
        if (g >= 3u) {
            int arr[4] = {0, 1, 2, 3};
            for (int i = 3; i >= 1; --i) {
                unsigned mask = (unsigned)i;
                mask |= mask >> 1; mask |= mask >> 2; mask |= mask >> 4;
                unsigned j;
                do { j = host_mt_next(mt, &mti) & mask; } while (j > (unsigned)i);
                int t = arr[i]; arr[i] = arr[j]; arr[j] = t;
            }
            w0 = arr[0]; w1 = arr[1];
        } else {
            w0 = (int)(host_mt_next(mt, &mti) & 3u);
        }
        s->g[k] = (int)g; s->w0[k] = w0; s->w1[k] = w1;
        s->pi[k] = (g == 4u) ? -1 : p++;
    }
    // fixed gates: rx(gp0,w0), ry(gp1,w1), rz(gp2,w3), crx(gp3,0->2), H(3), SX(2), CNOT(3->0)
    int k = 50;
    s->g[k] = 0; s->w0[k] = 0; s->w1[k] = -1; s->pi[k] = -2; k++;
    s->g[k] = 1; s->w0[k] = 1; s->w1[k] = -1; s->pi[k] = -3; k++;
    s->g[k] = 2; s->w0[k] = 3; s->w1[k] = -1; s->pi[k] = -4; k++;
    s->g[k] = 3; s->w0[k] = 0; s->w1[k] = 2;  s->pi[k] = -5; k++;
    s->g[k] = 5; s->w0[k] = 3; s->w1[k] = -1; s->pi[k] = -1; k++;
    s->g[k] = 6; s->w0[k] = 2; s->w1[k] = -1; s->pi[k] = -1; k++;
    s->g[k] = 4; s->w0[k] = 3; s->w1[k] = 0;  s->pi[k] = -1; k++;
}

extern "C" void kernel_launch(void* const* d_in, const int* in_sizes, int n_in,
                              void* d_out, int out_size) {
    const float* x   = (const float*)d_in[0];
    const float* c1w = (const float*)d_in[1];
    const float* c1b = (const float*)d_in[2];
    const float* c2w = (const float*)d_in[3];
    const float* c2b = (const float*)d_in[4];
    const float* gp  = (const float*)d_in[5];
    const float* rp  = (const float*)d_in[6];
    const float* gam = (const float*)d_in[7];
    const float* bet = (const float*)d_in[8];
    const float* fcw = (const float*)d_in[9];
    const float* fcb = (const float*)d_in[10];

    int B = in_sizes[0] / 784;
    if (B > BMAX) B = BMAX;

    GateSpec spec;
    host_build_spec(&spec);

    k_setup<<<1, 64>>>(gp, rp, spec);
    k_main<<<B, 128>>>(x, c1w, c1b, c2w, c2b);
    k_reduce<<<1, 256>>>(gam, bet, fcw, fcb, (float*)d_out, B);
}

// round 11
// speedup vs baseline: 1.4482x; 1.0920x over previous
#include <cuda_runtime.h>
#include <math.h>
#include <string.h>

// ---------------------------------------------------------------------------
// FraudNATHybridModel — R11: R10 + shfl-butterfly k_setup (register-resident
// 16x16 state, one amplitude per lane; 2 SHFL.XOR per gate instead of
// LDS/STS round trips). k_main / k_reduce unchanged from R10.
// ---------------------------------------------------------------------------

#define BMAX 8192
#define NGATES 57

struct GateSpec {
    int g[NGATES];    // 0 rx, 1 ry, 2 rz, 3 crx, 4 cnot, 5 H, 6 SX
    int w0[NGATES];
    int w1[NGATES];
    int pi[NGATES];   // >=0: rand_params[pi]; -2-j: gate_params[j]; -1: none
};

__device__ float2 g_U[256];
__device__ float  g_z[BMAX * 4];

#define PACK2(out, lo, hi) \
    asm("mov.b64 %0, {%1, %2};" : "=l"(out) : "r"(__float_as_uint(lo)), "r"(__float_as_uint(hi)))
#define UNPACK2(lo, hi, in) \
    do { unsigned _ulo, _uhi; \
         asm("mov.b64 {%0, %1}, %2;" : "=r"(_ulo), "=r"(_uhi) : "l"(in)); \
         lo = __uint_as_float(_ulo); hi = __uint_as_float(_uhi); } while (0)
#define FMA2(acc, a, b) \
    asm("fma.rn.f32x2 %0, %1, %2, %0;" : "+l"(acc) : "l"(a), "l"(b))

__device__ __forceinline__ float2 cmul(float2 a, float2 b) {
    return make_float2(a.x * b.x - a.y * b.y, a.x * b.y + a.y * b.x);
}
__device__ __forceinline__ float2 cadd(float2 a, float2 b) {
    return make_float2(a.x + b.x, a.y + b.y);
}
__device__ __forceinline__ float2 cfma_(float2 a, float2 b, float2 c) {
    c.x += a.x * b.x - a.y * b.y;
    c.y += a.x * b.y + a.y * b.x;
    return c;
}

// ------------------------- K0: build U_post (shfl butterflies) -------------
__global__ void k_setup(const float* __restrict__ gate_params,
                        const float* __restrict__ rand_params,
                        GateSpec spec) {
    __shared__ float2 smat[NGATES][4];     // u00,u01,u10,u11
    int tid = threadIdx.x;

    if (tid < NGATES) {
        int g = spec.g[tid];
        int pi = spec.pi[tid];
        float t = 0.f;
        if (pi >= 0) t = rand_params[pi];
        else if (pi <= -2) t = gate_params[-2 - pi];
        float sn, cs;
        sincosf(0.5f * t, &sn, &cs);
        float2 u00, u01, u10, u11;
        if (g == 0 || g == 3) {            // rx / crx
            u00 = make_float2(cs, 0.f);  u01 = make_float2(0.f, -sn);
            u10 = make_float2(0.f, -sn); u11 = make_float2(cs, 0.f);
        } else if (g == 1) {               // ry
            u00 = make_float2(cs, 0.f);  u01 = make_float2(-sn, 0.f);
            u10 = make_float2(sn, 0.f);  u11 = make_float2(cs, 0.f);
        } else if (g == 2) {               // rz
            u00 = make_float2(cs, -sn);  u01 = make_float2(0.f, 0.f);
            u10 = make_float2(0.f, 0.f); u11 = make_float2(cs, sn);
        } else if (g == 4) {               // cnot
            u00 = make_float2(0.f, 0.f); u01 = make_float2(1.f, 0.f);
            u10 = make_float2(1.f, 0.f); u11 = make_float2(0.f, 0.f);
        } else if (g == 5) {               // H
            const float r = 0.70710678118654752f;
            u00 = make_float2(r, 0.f);   u01 = make_float2(r, 0.f);
            u10 = make_float2(r, 0.f);   u11 = make_float2(-r, 0.f);
        } else {                           // SX
            u00 = make_float2(0.5f, 0.5f);  u01 = make_float2(0.5f, -0.5f);
            u10 = make_float2(0.5f, -0.5f); u11 = make_float2(0.5f, 0.5f);
        }
        smat[tid][0] = u00; smat[tid][1] = u01;
        smat[tid][2] = u10; smat[tid][3] = u11;
    }
    __syncthreads();

    // 256 threads: warp w holds columns 2w (lanes 0-15) and 2w+1 (lanes 16-31);
    // lane's state index = lane & 15. One amplitude per lane, in registers.
    int lane = tid & 31;
    int col = (tid >> 5) * 2 + (lane >> 4);
    int state = lane & 15;
    float2 cur = make_float2(state == col ? 1.f : 0.f, 0.f);

    for (int k = 0; k < NGATES; k++) {
        int g = spec.g[k];
        int m, mc;
        if (g == 3 || g == 4) { mc = 8 >> spec.w0[k]; m = 8 >> spec.w1[k]; }
        else                  { mc = 0;              m = 8 >> spec.w0[k]; }
        float2 u00 = smat[k][0], u01 = smat[k][1];
        float2 u10 = smat[k][2], u11 = smat[k][3];
        float px = __shfl_xor_sync(0xffffffffu, cur.x, m);
        float py = __shfl_xor_sync(0xffffffffu, cur.y, m);
        float2 po = make_float2(px, py);
        bool hi = (state & m) != 0;
        float2 a = hi ? po : cur;   // amplitude with target bit = 0
        float2 b = hi ? cur : po;   // amplitude with target bit = 1
        float2 nv = hi ? cadd(cmul(u10, a), cmul(u11, b))
                       : cadd(cmul(u00, a), cmul(u01, b));
        bool apply = (mc == 0) | ((state & mc) != 0);
        if (apply) cur = nv;
    }
    g_U[state * 16 + col] = cur;
}

// ------------------------- K1: fused per-image pipeline (R4 verbatim) ------
__global__ __launch_bounds__(128) void k_main(const float* __restrict__ x,
                                              const float* __restrict__ w1,
                                              const float* __restrict__ b1,
                                              const float* __restrict__ w2,
                                              const float* __restrict__ b2) {
    __shared__ float sx[28 * 29];        // row stride 29 -> conflict-free
    __shared__ float sw1c[72];
    __shared__ float sb1[8];
    __shared__ float sh1[8 * 196];       // conv1 pooled output [8][14][14]
    __shared__ __align__(16) float sw2c2[1152];  // conv2 weights [k][oc]
    __shared__ float sb2[16];
    __shared__ float shm[16 * 14 * 7];   // conv2 horizontally-pooled rows
    __shared__ float spart[112];
    __shared__ float spool[16];
    __shared__ float2 sv[8];
    __shared__ float2 sphi[16];

    int tid = threadIdx.x;
    int b = blockIdx.x;
    const float* xb = x + (size_t)b * 784;

    for (int i = tid; i < 784; i += 128) {
        int r = i / 28, c = i % 28;
        sx[r * 29 + c] = xb[i];
    }
    for (int i = tid; i < 72; i += 128) sw1c[i] = w1[i];
    if (tid < 8) sb1[tid] = b1[tid];
    for (int i = tid; i < 1152; i += 128) {
        int k = i >> 4, oc = i & 15;
        sw2c2[i] = w2[oc * 72 + k];      // transpose to [k][oc]
    }
    if (tid < 16) sb2[tid] = b2[tid];
    __syncthreads();

    // ---- conv1 (1->8, 3x3 SAME) + relu + maxpool2 -> sh1 ----
    if (tid < 112) {
        int c = tid / 14, y = tid % 14;
        float om[14];
#pragma unroll
        for (int i = 0; i < 14; i++) om[i] = 0.f;   // relu >= 0
        float bias = sb1[c];
#pragma unroll
        for (int dy = 0; dy < 2; dy++) {
            int rrow = 2 * y + dy;
            float cr[28];
#pragma unroll
            for (int i = 0; i < 28; i++) cr[i] = bias;
#pragma unroll
            for (int ky = 0; ky < 3; ky++) {
                int iy = rrow + ky - 1;
                if (iy >= 0 && iy < 28) {
                    float rb[30];
                    rb[0] = 0.f; rb[29] = 0.f;
#pragma unroll
                    for (int i = 0; i < 28; i++) rb[i + 1] = sx[iy * 29 + i];
#pragma unroll
                    for (int kx = 0; kx < 3; kx++) {
                        float w = sw1c[c * 9 + ky * 3 + kx];
#pragma unroll
                        for (int i = 0; i < 28; i++) cr[i] += w * rb[i + kx];
                    }
                }
            }
#pragma unroll
            for (int i = 0; i < 14; i++)
                om[i] = fmaxf(om[i], fmaxf(cr[2 * i], cr[2 * i + 1]));
        }
#pragma unroll
        for (int i = 0; i < 14; i++) sh1[(c * 14 + y) * 14 + i] = om[i];
    }
    __syncthreads();

    // ---- conv2 (8->16) packed f32x2 over channel pairs + horiz pooling ----
    if (tid < 112) {
        int cp = tid / 14, y = tid % 14;
        unsigned long long acc[14];
        {
            unsigned long long bias2;
            PACK2(bias2, sb2[2 * cp], sb2[2 * cp + 1]);
#pragma unroll
            for (int i = 0; i < 14; i++) acc[i] = bias2;
        }
#pragma unroll
        for (int ic = 0; ic < 8; ic++) {
#pragma unroll
            for (int ky = 0; ky < 3; ky++) {
                int iy = y + ky - 1;
                if (iy >= 0 && iy < 14) {
                    unsigned long long rp[16];
                    rp[0] = 0ull; rp[15] = 0ull;
#pragma unroll
                    for (int i = 0; i < 14; i++) {
                        float v = sh1[(ic * 14 + iy) * 14 + i];
                        PACK2(rp[i + 1], v, v);
                    }
#pragma unroll
                    for (int kx = 0; kx < 3; kx++) {
                        float2 wf = *(const float2*)&sw2c2[((ic * 3 + ky) * 3 + kx) * 16 + 2 * cp];
                        unsigned long long w2p;
                        PACK2(w2p, wf.x, wf.y);
#pragma unroll
                        for (int i = 0; i < 14; i++)
                            FMA2(acc[i], w2p, rp[i + kx]);
                    }
                }
            }
        }
        // unpack + horizontal max of adjacent pairs (relu deferred)
#pragma unroll
        for (int i = 0; i < 7; i++) {
            float a0l, a1l, a0h, a1h;
            UNPACK2(a0l, a1l, acc[2 * i]);
            UNPACK2(a0h, a1h, acc[2 * i + 1]);
            shm[((2 * cp) * 14 + y) * 7 + i]     = fmaxf(a0l, a0h);
            shm[((2 * cp + 1) * 14 + y) * 7 + i] = fmaxf(a1l, a1h);
        }
    }
    __syncthreads();

    // ---- vertical max of row pairs + relu + row sum -> spart ----
    if (tid < 112) {
        int c = tid / 7, y2 = tid % 7;
        const float* r0 = &shm[(c * 14 + 2 * y2) * 7];
        const float* r1 = r0 + 7;
        float psum = 0.f;
#pragma unroll
        for (int i = 0; i < 7; i++)
            psum += fmaxf(fmaxf(r0[i], r1[i]), 0.f);
        spart[c * 7 + y2] = psum;
    }
    __syncthreads();

    if (tid < 16) {
        float s = 0.f;
#pragma unroll
        for (int j = 0; j < 7; j++) s += spart[tid * 7 + j];
        spool[tid] = s * (1.f / 49.f);
    }
    __syncthreads();

    // ---- quantum: product-state encoder, psi = U_post * phi, Z expectations
    if (tid < 32) {
        int lane = tid;
        if (lane < 4) {
            float aa = spool[lane], bb = spool[4 + lane],
                  cc = spool[8 + lane], dd = spool[12 + lane];
            float sa, ca, sb, cb, sc, ccs, sd, cd;
            sincosf(0.5f * aa, &sa, &ca);
            sincosf(0.5f * bb, &sb, &cb);
            sincosf(0.5f * cc, &sc, &ccs);
            sincosf(0.5f * dd, &sd, &cd);
            float2 v0 = make_float2(ca * cb, -ca * sb);
            float2 v1 = make_float2(sa * cb, sa * sb);
            float2 t0 = make_float2(ccs * v0.x + sc * v1.y, ccs * v0.y - sc * v1.x);
            float2 t1 = make_float2(sc * v0.y + ccs * v1.x, -sc * v0.x + ccs * v1.y);
            float2 u0 = make_float2(cd * t0.x - sd * t1.x, cd * t0.y - sd * t1.y);
            float2 u1 = make_float2(sd * t0.x + cd * t1.x, sd * t0.y + cd * t1.y);
            sv[2 * lane] = u0;
            sv[2 * lane + 1] = u1;
        }
        __syncwarp();
        if (lane < 16) {
            float2 f0 = sv[0 + ((lane >> 3) & 1)];
            float2 f1 = sv[2 + ((lane >> 2) & 1)];
            float2 f2 = sv[4 + ((lane >> 1) & 1)];
            float2 f3 = sv[6 + (lane & 1)];
            sphi[lane] = cmul(cmul(f0, f1), cmul(f2, f3));
        }
        __syncwarp();
        float p = 0.f;
        if (lane < 16) {
            float2 psi = make_float2(0.f, 0.f);
#pragma unroll
            for (int j = 0; j < 16; j++) psi = cfma_(g_U[lane * 16 + j], sphi[j], psi);
            p = psi.x * psi.x + psi.y * psi.y;
        }
#pragma unroll
        for (int w = 0; w < 4; w++) {
            float sgn = ((lane >> (3 - w)) & 1) ? -p : p;
#pragma unroll
            for (int off = 16; off > 0; off >>= 1)
                sgn += __shfl_xor_sync(0xffffffffu, sgn, off);
            if (lane == 0) g_z[b * 4 + w] = sgn;
        }
    }
}

// --------------- K2: BN stats + fold + write outputs (merged) --------------
__global__ void k_reduce(const float* __restrict__ gam, const float* __restrict__ bet,
                         const float* __restrict__ fcw, const float* __restrict__ fcb,
                         float* __restrict__ out, int B) {
    __shared__ double red[256 * 8];
    __shared__ float scoef[5];
    int tid = threadIdx.x;
    double sm[4] = {0, 0, 0, 0}, sq[4] = {0, 0, 0, 0};
    for (int r = tid; r < B; r += 256) {
#pragma unroll
        for (int j = 0; j < 4; j++) {
            double v = (double)g_z[r * 4 + j];
            sm[j] += v;
            sq[j] += v * v;
        }
    }
#pragma unroll
    for (int j = 0; j < 4; j++) { red[tid * 8 + j] = sm[j]; red[tid * 8 + 4 + j] = sq[j]; }
    __syncthreads();
    for (int s = 128; s > 0; s >>= 1) {
        if (tid < s) {
#pragma unroll
            for (int j = 0; j < 8; j++) red[tid * 8 + j] += red[(tid + s) * 8 + j];
        }
        __syncthreads();
    }
    if (tid == 0) {
        double invB = 1.0 / (double)B;
        double csum = (double)fcb[0];
        for (int j = 0; j < 4; j++) {
            double mu = red[j] * invB;
            double var = red[4 + j] * invB - mu * mu;
            double sc = (double)gam[j] / sqrt(var + 1e-5);
            scoef[j] = (float)((double)fcw[j] * sc);
            csum += (double)fcw[j] * ((double)bet[j] - mu * sc);
        }
        scoef[4] = (float)csum;
    }
    __syncthreads();
    float c0 = scoef[0], c1 = scoef[1], c2 = scoef[2], c3 = scoef[3], c4 = scoef[4];
    for (int b = tid; b < B; b += 256) {
        out[b] = c4 + c0 * g_z[b * 4 + 0] + c1 * g_z[b * 4 + 1]
                    + c2 * g_z[b * 4 + 2] + c3 * g_z[b * 4 + 3];
    }
}

// ------------------- host-side MT19937 spec generation ---------------------
static unsigned host_mt_next(unsigned* mt, int* mti) {
    if (*mti >= 624) {
        for (int i = 0; i < 624; i++) {
            unsigned y = (mt[i] & 0x80000000u) | (mt[(i + 1) % 624] & 0x7fffffffu);
            unsigned v = mt[(i + 397) % 624] ^ (y >> 1);
            if (y & 1u) v ^= 0x9908b0dfu;
            mt[i] = v;
        }
        *mti = 0;
    }
    unsigned y = mt[(*mti)++];
    y ^= y >> 11;
    y ^= (y << 7) & 0x9d2c5680u;
    y ^= (y << 15) & 0xefc60000u;
    y ^= y >> 18;
    return y;
}

static void host_build_spec(GateSpec* s) {
    unsigned mt[624];
    mt[0] = 12345u;
    for (int i = 1; i < 624; i++)
        mt[i] = 1812433253u * (mt[i - 1] ^ (mt[i - 1] >> 30)) + (unsigned)i;
    int mti = 624;
    int p = 0;
    for (int k = 0; k < 50; k++) {
        unsigned g;
        do { g = host_mt_next(mt, &mti) & 7u; } while (g > 4u);
        int w0, w1 = -1;
        if (g >= 3u) {
            int arr[4] = {0, 1, 2, 3};
            for (int i = 3; i >= 1; --i) {
                unsigned mask = (unsigned)i;
                mask |= mask >> 1; mask |= mask >> 2; mask |= mask >> 4;
                unsigned j;
                do { j = host_mt_next(mt, &mti) & mask; } while (j > (unsigned)i);
                int t = arr[i]; arr[i] = arr[j]; arr[j] = t;
            }
            w0 = arr[0]; w1 = arr[1];
        } else {
            w0 = (int)(host_mt_next(mt, &mti) & 3u);
        }
        s->g[k] = (int)g; s->w0[k] = w0; s->w1[k] = w1;
        s->pi[k] = (g == 4u) ? -1 : p++;
    }
    // fixed gates: rx(gp0,w0), ry(gp1,w1), rz(gp2,w3), crx(gp3,0->2), H(3), SX(2), CNOT(3->0)
    int k = 50;
    s->g[k] = 0; s->w0[k] = 0; s->w1[k] = -1; s->pi[k] = -2; k++;
    s->g[k] = 1; s->w0[k] = 1; s->w1[k] = -1; s->pi[k] = -3; k++;
    s->g[k] = 2; s->w0[k] = 3; s->w1[k] = -1; s->pi[k] = -4; k++;
    s->g[k] = 3; s->w0[k] = 0; s->w1[k] = 2;  s->pi[k] = -5; k++;
    s->g[k] = 5; s->w0[k] = 3; s->w1[k] = -1; s->pi[k] = -1; k++;
    s->g[k] = 6; s->w0[k] = 2; s->w1[k] = -1; s->pi[k] = -1; k++;
    s->g[k] = 4; s->w0[k] = 3; s->w1[k] = 0;  s->pi[k] = -1; k++;
}

extern "C" void kernel_launch(void* const* d_in, const int* in_sizes, int n_in,
                              void* d_out, int out_size) {
    const float* x   = (const float*)d_in[0];
    const float* c1w = (const float*)d_in[1];
    const float* c1b = (const float*)d_in[2];
    const float* c2w = (const float*)d_in[3];
    const float* c2b = (const float*)d_in[4];
    const float* gp  = (const float*)d_in[5];
    const float* rp  = (const float*)d_in[6];
    const float* gam = (const float*)d_in[7];
    const float* bet = (const float*)d_in[8];
    const float* fcw = (const float*)d_in[9];
    const float* fcb = (const float*)d_in[10];

    int B = in_sizes[0] / 784;
    if (B > BMAX) B = BMAX;

    GateSpec spec;
    host_build_spec(&spec);

    k_setup<<<1, 256>>>(gp, rp, spec);
    k_main<<<B, 128>>>(x, c1w, c1b, c2w, c2b);
    k_reduce<<<1, 256>>>(gam, bet, fcw, fcb, (float*)d_out, B);
}

// round 12
// speedup vs baseline: 1.4536x; 1.0038x over previous
#include <cuda_runtime.h>
#include <math.h>
#include <string.h>

// ---------------------------------------------------------------------------
// FraudNATHybridModel — R12: R11 + packed-f32x2 conv1 (isolated; writes into
// R4-layout sh1 so conv2 is byte-identical to best-known) + 512-thread reduce.
// ---------------------------------------------------------------------------

#define BMAX 8192
#define NGATES 57

struct GateSpec {
    int g[NGATES];    // 0 rx, 1 ry, 2 rz, 3 crx, 4 cnot, 5 H, 6 SX
    int w0[NGATES];
    int w1[NGATES];
    int pi[NGATES];   // >=0: rand_params[pi]; -2-j: gate_params[j]; -1: none
};

__device__ float2 g_U[256];
__device__ float  g_z[BMAX * 4];

#define PACK2(out, lo, hi) \
    asm("mov.b64 %0, {%1, %2};" : "=l"(out) : "r"(__float_as_uint(lo)), "r"(__float_as_uint(hi)))
#define UNPACK2(lo, hi, in) \
    do { unsigned _ulo, _uhi; \
         asm("mov.b64 {%0, %1}, %2;" : "=r"(_ulo), "=r"(_uhi) : "l"(in)); \
         lo = __uint_as_float(_ulo); hi = __uint_as_float(_uhi); } while (0)
#define FMA2(acc, a, b) \
    asm("fma.rn.f32x2 %0, %1, %2, %0;" : "+l"(acc) : "l"(a), "l"(b))

__device__ __forceinline__ unsigned long long lds64(const void* p) {
    unsigned long long v;
    unsigned a = (unsigned)__cvta_generic_to_shared(p);
    asm("ld.shared.b64 %0, [%1];" : "=l"(v) : "r"(a));
    return v;
}

__device__ __forceinline__ float2 cmul(float2 a, float2 b) {
    return make_float2(a.x * b.x - a.y * b.y, a.x * b.y + a.y * b.x);
}
__device__ __forceinline__ float2 cadd(float2 a, float2 b) {
    return make_float2(a.x + b.x, a.y + b.y);
}
__device__ __forceinline__ float2 cfma_(float2 a, float2 b, float2 c) {
    c.x += a.x * b.x - a.y * b.y;
    c.y += a.x * b.y + a.y * b.x;
    return c;
}

// ------------------------- K0: build U_post (shfl butterflies) -------------
__global__ void k_setup(const float* __restrict__ gate_params,
                        const float* __restrict__ rand_params,
                        GateSpec spec) {
    __shared__ float2 smat[NGATES][4];     // u00,u01,u10,u11
    int tid = threadIdx.x;

    if (tid < NGATES) {
        int g = spec.g[tid];
        int pi = spec.pi[tid];
        float t = 0.f;
        if (pi >= 0) t = rand_params[pi];
        else if (pi <= -2) t = gate_params[-2 - pi];
        float sn, cs;
        sincosf(0.5f * t, &sn, &cs);
        float2 u00, u01, u10, u11;
        if (g == 0 || g == 3) {            // rx / crx
            u00 = make_float2(cs, 0.f);  u01 = make_float2(0.f, -sn);
            u10 = make_float2(0.f, -sn); u11 = make_float2(cs, 0.f);
        } else if (g == 1) {               // ry
            u00 = make_float2(cs, 0.f);  u01 = make_float2(-sn, 0.f);
            u10 = make_float2(sn, 0.f);  u11 = make_float2(cs, 0.f);
        } else if (g == 2) {               // rz
            u00 = make_float2(cs, -sn);  u01 = make_float2(0.f, 0.f);
            u10 = make_float2(0.f, 0.f); u11 = make_float2(cs, sn);
        } else if (g == 4) {               // cnot
            u00 = make_float2(0.f, 0.f); u01 = make_float2(1.f, 0.f);
            u10 = make_float2(1.f, 0.f); u11 = make_float2(0.f, 0.f);
        } else if (g == 5) {               // H
            const float r = 0.70710678118654752f;
            u00 = make_float2(r, 0.f);   u01 = make_float2(r, 0.f);
            u10 = make_float2(r, 0.f);   u11 = make_float2(-r, 0.f);
        } else {                           // SX
            u00 = make_float2(0.5f, 0.5f);  u01 = make_float2(0.5f, -0.5f);
            u10 = make_float2(0.5f, -0.5f); u11 = make_float2(0.5f, 0.5f);
        }
        smat[tid][0] = u00; smat[tid][1] = u01;
        smat[tid][2] = u10; smat[tid][3] = u11;
    }
    __syncthreads();

    int lane = tid & 31;
    int col = (tid >> 5) * 2 + (lane >> 4);
    int state = lane & 15;
    float2 cur = make_float2(state == col ? 1.f : 0.f, 0.f);

    for (int k = 0; k < NGATES; k++) {
        int g = spec.g[k];
        int m, mc;
        if (g == 3 || g == 4) { mc = 8 >> spec.w0[k]; m = 8 >> spec.w1[k]; }
        else                  { mc = 0;              m = 8 >> spec.w0[k]; }
        float2 u00 = smat[k][0], u01 = smat[k][1];
        float2 u10 = smat[k][2], u11 = smat[k][3];
        float px = __shfl_xor_sync(0xffffffffu, cur.x, m);
        float py = __shfl_xor_sync(0xffffffffu, cur.y, m);
        float2 po = make_float2(px, py);
        bool hi = (state & m) != 0;
        float2 a = hi ? po : cur;
        float2 b = hi ? cur : po;
        float2 nv = hi ? cadd(cmul(u10, a), cmul(u11, b))
                       : cadd(cmul(u00, a), cmul(u01, b));
        bool apply = (mc == 0) | ((state & mc) != 0);
        if (apply) cur = nv;
    }
    g_U[state * 16 + col] = cur;
}

// ------------------------- K1: fused per-image pipeline --------------------
__global__ __launch_bounds__(128) void k_main(const float* __restrict__ x,
                                              const float* __restrict__ w1,
                                              const float* __restrict__ b1,
                                              const float* __restrict__ w2,
                                              const float* __restrict__ b2) {
    __shared__ __align__(16) float2 sxp[29][31];  // (x[j-1][c-1], x[j][c-1]), zero-padded
    __shared__ float2 sw1p[72];          // (w,w)
    __shared__ float2 sb1p[8];           // (b,b)
    __shared__ float sh1[8 * 196];       // conv1 pooled output [8][14][14]
    __shared__ __align__(16) float sw2c2[1152];  // conv2 weights [k][oc]
    __shared__ float sb2[16];
    __shared__ float shm[16 * 14 * 7];   // conv2 horizontally-pooled rows
    __shared__ float spart[112];
    __shared__ float spool[16];
    __shared__ float2 sv[8];
    __shared__ float2 sphi[16];

    int tid = threadIdx.x;
    int b = blockIdx.x;
    const float* xb = x + (size_t)b * 784;

    // zero sxp
    {
        float2 z2 = make_float2(0.f, 0.f);
        float2* p1 = &sxp[0][0];
        for (int i = tid; i < 29 * 31; i += 128) p1[i] = z2;
    }
    for (int i = tid; i < 72; i += 128) { float w = w1[i]; sw1p[i] = make_float2(w, w); }
    if (tid < 8)  { float v = b1[tid]; sb1p[tid] = make_float2(v, v); }
    for (int i = tid; i < 1152; i += 128) {
        int k = i >> 4, oc = i & 15;
        sw2c2[i] = w2[oc * 72 + k];      // transpose to [k][oc]
    }
    if (tid < 16) sb2[tid] = b2[tid];
    __syncthreads();

    // scatter input into vertical pairs
    for (int i = tid; i < 784; i += 128) {
        int r = i / 28, c = i % 28;
        float v = xb[i];
        sxp[r + 1][c + 1].x = v;
        sxp[r][c + 1].y = v;
    }
    __syncthreads();

    // ---- conv1 (packed vertical row pairs) + relu + maxpool -> sh1 ----
    if (tid < 112) {
        int c = tid / 14, y = tid % 14;
        unsigned long long wp[9];
#pragma unroll
        for (int k = 0; k < 9; k++) wp[k] = lds64(&sw1p[c * 9 + k]);
        unsigned long long bias2 = lds64(&sb1p[c]);
        float pooled[14];
#pragma unroll
        for (int h = 0; h < 2; h++) {
            unsigned long long cr[14];
#pragma unroll
            for (int i = 0; i < 14; i++) cr[i] = bias2;
#pragma unroll
            for (int ky = 0; ky < 3; ky++) {
                int j = 2 * y + ky;
                unsigned long long rp[16];
#pragma unroll
                for (int i = 0; i < 16; i++) rp[i] = lds64(&sxp[j][14 * h + i]);
#pragma unroll
                for (int kx = 0; kx < 3; kx++) {
                    unsigned long long w = wp[ky * 3 + kx];
#pragma unroll
                    for (int i = 0; i < 14; i++) FMA2(cr[i], w, rp[i + kx]);
                }
            }
#pragma unroll
            for (int o = 0; o < 7; o++) {
                float l0, h0, l1, h1;
                UNPACK2(l0, h0, cr[2 * o]);
                UNPACK2(l1, h1, cr[2 * o + 1]);
                pooled[h * 7 + o] = fmaxf(fmaxf(fmaxf(l0, h0), fmaxf(l1, h1)), 0.f);
            }
        }
        float* row = &sh1[(c * 14 + y) * 14];
#pragma unroll
        for (int i = 0; i < 14; i++) row[i] = pooled[i];
    }
    __syncthreads();

    // ---- conv2 (8->16) packed f32x2 over channel pairs (R4 verbatim) ----
    if (tid < 112) {
        int cp = tid / 14, y = tid % 14;
        unsigned long long acc[14];
        {
            unsigned long long bias2;
            PACK2(bias2, sb2[2 * cp], sb2[2 * cp + 1]);
#pragma unroll
            for (int i = 0; i < 14; i++) acc[i] = bias2;
        }
#pragma unroll
        for (int ic = 0; ic < 8; ic++) {
#pragma unroll
            for (int ky = 0; ky < 3; ky++) {
                int iy = y + ky - 1;
                if (iy >= 0 && iy < 14) {
                    unsigned long long rp[16];
                    rp[0] = 0ull; rp[15] = 0ull;
#pragma unroll
                    for (int i = 0; i < 14; i++) {
                        float v = sh1[(ic * 14 + iy) * 14 + i];
                        PACK2(rp[i + 1], v, v);
                    }
#pragma unroll
                    for (int kx = 0; kx < 3; kx++) {
                        float2 wf = *(const float2*)&sw2c2[((ic * 3 + ky) * 3 + kx) * 16 + 2 * cp];
                        unsigned long long w2p;
                        PACK2(w2p, wf.x, wf.y);
#pragma unroll
                        for (int i = 0; i < 14; i++)
                            FMA2(acc[i], w2p, rp[i + kx]);
                    }
                }
            }
        }
#pragma unroll
        for (int i = 0; i < 7; i++) {
            float a0l, a1l, a0h, a1h;
            UNPACK2(a0l, a1l, acc[2 * i]);
            UNPACK2(a0h, a1h, acc[2 * i + 1]);
            shm[((2 * cp) * 14 + y) * 7 + i]     = fmaxf(a0l, a0h);
            shm[((2 * cp + 1) * 14 + y) * 7 + i] = fmaxf(a1l, a1h);
        }
    }
    __syncthreads();

    // ---- vertical max of row pairs + relu + row sum -> spart ----
    if (tid < 112) {
        int c = tid / 7, y2 = tid % 7;
        const float* r0 = &shm[(c * 14 + 2 * y2) * 7];
        const float* r1 = r0 + 7;
        float psum = 0.f;
#pragma unroll
        for (int i = 0; i < 7; i++)
            psum += fmaxf(fmaxf(r0[i], r1[i]), 0.f);
        spart[c * 7 + y2] = psum;
    }
    __syncthreads();

    if (tid < 16) {
        float s = 0.f;
#pragma unroll
        for (int j = 0; j < 7; j++) s += spart[tid * 7 + j];
        spool[tid] = s * (1.f / 49.f);
    }
    __syncthreads();

    // ---- quantum: product-state encoder, psi = U_post * phi, Z expectations
    if (tid < 32) {
        int lane = tid;
        if (lane < 4) {
            float aa = spool[lane], bb = spool[4 + lane],
                  cc = spool[8 + lane], dd = spool[12 + lane];
            float sa, ca, sb, cb, sc, ccs, sd, cd;
            sincosf(0.5f * aa, &sa, &ca);
            sincosf(0.5f * bb, &sb, &cb);
            sincosf(0.5f * cc, &sc, &ccs);
            sincosf(0.5f * dd, &sd, &cd);
            float2 v0 = make_float2(ca * cb, -ca * sb);
            float2 v1 = make_float2(sa * cb, sa * sb);
            float2 t0 = make_float2(ccs * v0.x + sc * v1.y, ccs * v0.y - sc * v1.x);
            float2 t1 = make_float2(sc * v0.y + ccs * v1.x, -sc * v0.x + ccs * v1.y);
            float2 u0 = make_float2(cd * t0.x - sd * t1.x, cd * t0.y - sd * t1.y);
            float2 u1 = make_float2(sd * t0.x + cd * t1.x, sd * t0.y + cd * t1.y);
            sv[2 * lane] = u0;
            sv[2 * lane + 1] = u1;
        }
        __syncwarp();
        if (lane < 16) {
            float2 f0 = sv[0 + ((lane >> 3) & 1)];
            float2 f1 = sv[2 + ((lane >> 2) & 1)];
            float2 f2 = sv[4 + ((lane >> 1) & 1)];
            float2 f3 = sv[6 + (lane & 1)];
            sphi[lane] = cmul(cmul(f0, f1), cmul(f2, f3));
        }
        __syncwarp();
        float p = 0.f;
        if (lane < 16) {
            float2 psi = make_float2(0.f, 0.f);
#pragma unroll
            for (int j = 0; j < 16; j++) psi = cfma_(g_U[lane * 16 + j], sphi[j], psi);
            p = psi.x * psi.x + psi.y * psi.y;
        }
#pragma unroll
        for (int w = 0; w < 4; w++) {
            float sgn = ((lane >> (3 - w)) & 1) ? -p : p;
#pragma unroll
            for (int off = 16; off > 0; off >>= 1)
                sgn += __shfl_xor_sync(0xffffffffu, sgn, off);
            if (lane == 0) g_z[b * 4 + w] = sgn;
        }
    }
}

// --------------- K2: BN stats + fold + write outputs (merged) --------------
#define RT 512
__global__ void k_reduce(const float* __restrict__ gam, const float* __restrict__ bet,
                         const float* __restrict__ fcw, const float* __restrict__ fcb,
                         float* __restrict__ out, int B) {
    __shared__ double red[RT * 8];
    __shared__ float scoef[5];
    int tid = threadIdx.x;
    double sm[4] = {0, 0, 0, 0}, sq[4] = {0, 0, 0, 0};
    for (int r = tid; r < B; r += RT) {
#pragma unroll
        for (int j = 0; j < 4; j++) {
            double v = (double)g_z[r * 4 + j];
            sm[j] += v;
            sq[j] += v * v;
        }
    }
#pragma unroll
    for (int j = 0; j < 4; j++) { red[tid * 8 + j] = sm[j]; red[tid * 8 + 4 + j] = sq[j]; }
    __syncthreads();
    for (int s = RT / 2; s > 0; s >>= 1) {
        if (tid < s) {
#pragma unroll
            for (int j = 0; j < 8; j++) red[tid * 8 + j] += red[(tid + s) * 8 + j];
        }
        __syncthreads();
    }
    if (tid == 0) {
        double invB = 1.0 / (double)B;
        double csum = (double)fcb[0];
        for (int j = 0; j < 4; j++) {
            double mu = red[j] * invB;
            double var = red[4 + j] * invB - mu * mu;
            double sc = (double)gam[j] / sqrt(var + 1e-5);
            scoef[j] = (float)((double)fcw[j] * sc);
            csum += (double)fcw[j] * ((double)bet[j] - mu * sc);
        }
        scoef[4] = (float)csum;
    }
    __syncthreads();
    float c0 = scoef[0], c1 = scoef[1], c2 = scoef[2], c3 = scoef[3], c4 = scoef[4];
    for (int b = tid; b < B; b += RT) {
        out[b] = c4 + c0 * g_z[b * 4 + 0] + c1 * g_z[b * 4 + 1]
                    + c2 * g_z[b * 4 + 2] + c3 * g_z[b * 4 + 3];
    }
}

// ------------------- host-side MT19937 spec generation ---------------------
static unsigned host_mt_next(unsigned* mt, int* mti) {
    if (*mti >= 624) {
        for (int i = 0; i < 624; i++) {
            unsigned y = (mt[i] & 0x80000000u) | (mt[(i + 1) % 624] & 0x7fffffffu);
            unsigned v = mt[(i + 397) % 624] ^ (y >> 1);
            if (y & 1u) v ^= 0x9908b0dfu;
            mt[i] = v;
        }
        *mti = 0;
    }
    unsigned y = mt[(*mti)++];
    y ^= y >> 11;
    y ^= (y << 7) & 0x9d2c5680u;
    y ^= (y << 15) & 0xefc60000u;
    y ^= y >> 18;
    return y;
}

static void host_build_spec(GateSpec* s) {
    unsigned mt[624];
    mt[0] = 12345u;
    for (int i = 1; i < 624; i++)
        mt[i] = 1812433253u * (mt[i - 1] ^ (mt[i - 1] >> 30)) + (unsigned)i;
    int mti = 624;
    int p = 0;
    for (int k = 0; k < 50; k++) {
        unsigned g;
        do { g = host_mt_next(mt, &mti) & 7u; } while (g > 4u);
        int w0, w1 = -1;
        if (g >= 3u) {
            int arr[4] = {0, 1, 2, 3};
            for (int i = 3; i >= 1; --i) {
                unsigned mask = (unsigned)i;
                mask |= mask >> 1; mask |= mask >> 2; mask |= mask >> 4;
                unsigned j;
                do { j = host_mt_next(mt, &mti) & mask; } while (j > (unsigned)i);
                int t = arr[i]; arr[i] = arr[j]; arr[j] = t;
            }
            w0 = arr[0]; w1 = arr[1];
        } else {
            w0 = (int)(host_mt_next(mt, &mti) & 3u);
        }
        s->g[k] = (int)g; s->w0[k] = w0; s->w1[k] = w1;
        s->pi[k] = (g == 4u) ? -1 : p++;
    }
    // fixed: rx(gp0,w0), ry(gp1,w1), rz(gp2,w3), crx(gp3,0->2), H(3), SX(2), CNOT(3->0)
    int k = 50;
    s->g[k] = 0; s->w0[k] = 0; s->w1[k] = -1; s->pi[k] = -2; k++;
    s->g[k] = 1; s->w0[k] = 1; s->w1[k] = -1; s->pi[k] = -3; k++;
    s->g[k] = 2; s->w0[k] = 3; s->w1[k] = -1; s->pi[k] = -4; k++;
    s->g[k] = 3; s->w0[k] = 0; s->w1[k] = 2;  s->pi[k] = -5; k++;
    s->g[k] = 5; s->w0[k] = 3; s->w1[k] = -1; s->pi[k] = -1; k++;
    s->g[k] = 6; s->w0[k] = 2; s->w1[k] = -1; s->pi[k] = -1; k++;
    s->g[k] = 4; s->w0[k] = 3; s->w1[k] = 0;  s->pi[k] = -1; k++;
}

extern "C" void kernel_launch(void* const* d_in, const int* in_sizes, int n_in,
                              void* d_out, int out_size) {
    const float* x   = (const float*)d_in[0];
    const float* c1w = (const float*)d_in[1];
    const float* c1b = (const float*)d_in[2];
    const float* c2w = (const float*)d_in[3];
    const float* c2b = (const float*)d_in[4];
    const float* gp  = (const float*)d_in[5];
    const float* rp  = (const float*)d_in[6];
    const float* gam = (const float*)d_in[7];
    const float* bet = (const float*)d_in[8];
    const float* fcw = (const float*)d_in[9];
    const float* fcb = (const float*)d_in[10];

    int B = in_sizes[0] / 784;
    if (B > BMAX) B = BMAX;

    GateSpec spec;
    host_build_spec(&spec);

    k_setup<<<1, 256>>>(gp, rp, spec);
    k_main<<<B, 128>>>(x, c1w, c1b, c2w, c2b);
    k_reduce<<<1, RT>>>(gam, bet, fcw, fcb, (float*)d_out, B);
}

// round 16
// speedup vs baseline: 1.5062x; 1.0362x over previous
#include <cuda_runtime.h>
#include <math.h>
#include <string.h>

// ---------------------------------------------------------------------------
// FraudNATHybridModel — R14: R13 with the k_quant mask-precedence bug fixed
// (m = 8 >> w0, not 8 >> (8 >> w0)). k_setup deleted; k_main ends at pooled
// features; k_quant recomputes U per-block (shfl butterflies) and processes
// 4 images per warp; merged reduce+output.
// ---------------------------------------------------------------------------

#define BMAX 8192
#define NGATES 57

struct GateSpec {
    int g[NGATES];    // 0 rx, 1 ry, 2 rz, 3 crx, 4 cnot, 5 H, 6 SX
    int w0[NGATES];
    int w1[NGATES];
    int pi[NGATES];   // >=0: rand_params[pi]; -2-j: gate_params[j]; -1: none
};

__device__ float  g_pool[BMAX * 16];
__device__ float  g_z[BMAX * 4];

#define PACK2(out, lo, hi) \
    asm("mov.b64 %0, {%1, %2};" : "=l"(out) : "r"(__float_as_uint(lo)), "r"(__float_as_uint(hi)))
#define UNPACK2(lo, hi, in) \
    do { unsigned _ulo, _uhi; \
         asm("mov.b64 {%0, %1}, %2;" : "=r"(_ulo), "=r"(_uhi) : "l"(in)); \
         lo = __uint_as_float(_ulo); hi = __uint_as_float(_uhi); } while (0)
#define FMA2(acc, a, b) \
    asm("fma.rn.f32x2 %0, %1, %2, %0;" : "+l"(acc) : "l"(a), "l"(b))

__device__ __forceinline__ unsigned long long lds64(const void* p) {
    unsigned long long v;
    unsigned a = (unsigned)__cvta_generic_to_shared(p);
    asm("ld.shared.b64 %0, [%1];" : "=l"(v) : "r"(a));
    return v;
}

__device__ __forceinline__ float2 cmul(float2 a, float2 b) {
    return make_float2(a.x * b.x - a.y * b.y, a.x * b.y + a.y * b.x);
}
__device__ __forceinline__ float2 cadd(float2 a, float2 b) {
    return make_float2(a.x + b.x, a.y + b.y);
}
__device__ __forceinline__ float2 cfma_(float2 a, float2 b, float2 c) {
    c.x += a.x * b.x - a.y * b.y;
    c.y += a.x * b.y + a.y * b.x;
    return c;
}

// ------------------------- K1: fused conv pipeline -------------------------
__global__ __launch_bounds__(128) void k_main(const float* __restrict__ x,
                                              const float* __restrict__ w1,
                                              const float* __restrict__ b1,
                                              const float* __restrict__ w2,
                                              const float* __restrict__ b2) {
    __shared__ __align__(16) float2 sxp[29][31];  // (x[j-1][c-1], x[j][c-1]), zero-padded
    __shared__ float2 sw1p[72];          // (w,w)
    __shared__ float2 sb1p[8];           // (b,b)
    __shared__ float sh1[8 * 196];       // conv1 pooled output [8][14][14]
    __shared__ __align__(16) float sw2c2[1152];  // conv2 weights [k][oc]
    __shared__ float sb2[16];
    __shared__ float shm[16 * 14 * 7];   // conv2 horizontally-pooled rows
    __shared__ float spart[112];

    int tid = threadIdx.x;
    int b = blockIdx.x;
    const float* xb = x + (size_t)b * 784;

    // zero sxp
    {
        float2 z2 = make_float2(0.f, 0.f);
        float2* p1 = &sxp[0][0];
        for (int i = tid; i < 29 * 31; i += 128) p1[i] = z2;
    }
    for (int i = tid; i < 72; i += 128) { float w = w1[i]; sw1p[i] = make_float2(w, w); }
    if (tid < 8)  { float v = b1[tid]; sb1p[tid] = make_float2(v, v); }
    for (int i = tid; i < 1152; i += 128) {
        int k = i >> 4, oc = i & 15;
        sw2c2[i] = w2[oc * 72 + k];      // transpose to [k][oc]
    }
    if (tid < 16) sb2[tid] = b2[tid];
    __syncthreads();

    // scatter input into vertical pairs
    for (int i = tid; i < 784; i += 128) {
        int r = i / 28, c = i % 28;
        float v = xb[i];
        sxp[r + 1][c + 1].x = v;
        sxp[r][c + 1].y = v;
    }
    __syncthreads();

    // ---- conv1 (packed vertical row pairs) + relu + maxpool -> sh1 ----
    if (tid < 112) {
        int c = tid / 14, y = tid % 14;
        unsigned long long wp[9];
#pragma unroll
        for (int k = 0; k < 9; k++) wp[k] = lds64(&sw1p[c * 9 + k]);
        unsigned long long bias2 = lds64(&sb1p[c]);
        float pooled[14];
#pragma unroll
        for (int h = 0; h < 2; h++) {
            unsigned long long cr[14];
#pragma unroll
            for (int i = 0; i < 14; i++) cr[i] = bias2;
#pragma unroll
            for (int ky = 0; ky < 3; ky++) {
                int j = 2 * y + ky;
                unsigned long long rp[16];
#pragma unroll
                for (int i = 0; i < 16; i++) rp[i] = lds64(&sxp[j][14 * h + i]);
#pragma unroll
                for (int kx = 0; kx < 3; kx++) {
                    unsigned long long w = wp[ky * 3 + kx];
#pragma unroll
                    for (int i = 0; i < 14; i++) FMA2(cr[i], w, rp[i + kx]);
                }
            }
#pragma unroll
            for (int o = 0; o < 7; o++) {
                float l0, h0, l1, h1;
                UNPACK2(l0, h0, cr[2 * o]);
                UNPACK2(l1, h1, cr[2 * o + 1]);
                pooled[h * 7 + o] = fmaxf(fmaxf(fmaxf(l0, h0), fmaxf(l1, h1)), 0.f);
            }
        }
        float* row = &sh1[(c * 14 + y) * 14];
#pragma unroll
        for (int i = 0; i < 14; i++) row[i] = pooled[i];
    }
    __syncthreads();

    // ---- conv2 (8->16) packed f32x2 over channel pairs ----
    if (tid < 112) {
        int cp = tid / 14, y = tid % 14;
        unsigned long long acc[14];
        {
            unsigned long long bias2;
            PACK2(bias2, sb2[2 * cp], sb2[2 * cp + 1]);
#pragma unroll
            for (int i = 0; i < 14; i++) acc[i] = bias2;
        }
#pragma unroll
        for (int ic = 0; ic < 8; ic++) {
#pragma unroll
            for (int ky = 0; ky < 3; ky++) {
                int iy = y + ky - 1;
                if (iy >= 0 && iy < 14) {
                    unsigned long long rp[16];
                    rp[0] = 0ull; rp[15] = 0ull;
#pragma unroll
                    for (int i = 0; i < 14; i++) {
                        float v = sh1[(ic * 14 + iy) * 14 + i];
                        PACK2(rp[i + 1], v, v);
                    }
#pragma unroll
                    for (int kx = 0; kx < 3; kx++) {
                        float2 wf = *(const float2*)&sw2c2[((ic * 3 + ky) * 3 + kx) * 16 + 2 * cp];
                        unsigned long long w2p;
                        PACK2(w2p, wf.x, wf.y);
#pragma unroll
                        for (int i = 0; i < 14; i++)
                            FMA2(acc[i], w2p, rp[i + kx]);
                    }
                }
            }
        }
#pragma unroll
        for (int i = 0; i < 7; i++) {
            float a0l, a1l, a0h, a1h;
            UNPACK2(a0l, a1l, acc[2 * i]);
            UNPACK2(a0h, a1h, acc[2 * i + 1]);
            shm[((2 * cp) * 14 + y) * 7 + i]     = fmaxf(a0l, a0h);
            shm[((2 * cp + 1) * 14 + y) * 7 + i] = fmaxf(a1l, a1h);
        }
    }
    __syncthreads();

    // ---- vertical max of row pairs + relu + row sum -> spart ----
    if (tid < 112) {
        int c = tid / 7, y2 = tid % 7;
        const float* r0 = &shm[(c * 14 + 2 * y2) * 7];
        const float* r1 = r0 + 7;
        float psum = 0.f;
#pragma unroll
        for (int i = 0; i < 7; i++)
            psum += fmaxf(fmaxf(r0[i], r1[i]), 0.f);
        spart[c * 7 + y2] = psum;
    }
    __syncthreads();

    if (tid < 16) {
        float s = 0.f;
#pragma unroll
        for (int j = 0; j < 7; j++) s += spart[tid * 7 + j];
        g_pool[b * 16 + tid] = s * (1.f / 49.f);
    }
}

// ---------------- K_quant: per-block U (shfl) + per-warp images ------------
#define QBLK 256
__global__ __launch_bounds__(QBLK) void k_quant(const float* __restrict__ gate_params,
                                                const float* __restrict__ rand_params,
                                                GateSpec spec, int B) {
    __shared__ float2 smat[NGATES][4];
    __shared__ float2 sU[16 * 17];       // U[row][col] at row*17+col (conflict-free)
    int tid = threadIdx.x;
    int lane = tid & 31;

    // ---- phase 1a: gate matrices ----
    if (tid < NGATES) {
        int g = spec.g[tid];
        int pi = spec.pi[tid];
        float t = 0.f;
        if (pi >= 0) t = rand_params[pi];
        else if (pi <= -2) t = gate_params[-2 - pi];
        float sn, cs;
        sincosf(0.5f * t, &sn, &cs);
        float2 u00, u01, u10, u11;
        if (g == 0 || g == 3) {
            u00 = make_float2(cs, 0.f);  u01 = make_float2(0.f, -sn);
            u10 = make_float2(0.f, -sn); u11 = make_float2(cs, 0.f);
        } else if (g == 1) {
            u00 = make_float2(cs, 0.f);  u01 = make_float2(-sn, 0.f);
            u10 = make_float2(sn, 0.f);  u11 = make_float2(cs, 0.f);
        } else if (g == 2) {
            u00 = make_float2(cs, -sn);  u01 = make_float2(0.f, 0.f);
            u10 = make_float2(0.f, 0.f); u11 = make_float2(cs, sn);
        } else if (g == 4) {
            u00 = make_float2(0.f, 0.f); u01 = make_float2(1.f, 0.f);
            u10 = make_float2(1.f, 0.f); u11 = make_float2(0.f, 0.f);
        } else if (g == 5) {
            const float r = 0.70710678118654752f;
            u00 = make_float2(r, 0.f);   u01 = make_float2(r, 0.f);
            u10 = make_float2(r, 0.f);   u11 = make_float2(-r, 0.f);
        } else {
            u00 = make_float2(0.5f, 0.5f);  u01 = make_float2(0.5f, -0.5f);
            u10 = make_float2(0.5f, -0.5f); u11 = make_float2(0.5f, 0.5f);
        }
        smat[tid][0] = u00; smat[tid][1] = u01;
        smat[tid][2] = u10; smat[tid][3] = u11;
    }
    __syncthreads();

    // ---- phase 1b: shfl-butterfly gate chain; 256 threads = 16x16 entries --
    {
        int col = (tid >> 5) * 2 + (lane >> 4);
        int state = lane & 15;
        float2 cur = make_float2(state == col ? 1.f : 0.f, 0.f);
        for (int k = 0; k < NGATES; k++) {
            int g = spec.g[k];
            int m, mc;
            if (g == 3 || g == 4) { mc = 8 >> spec.w0[k]; m = 8 >> spec.w1[k]; }
            else                  { mc = 0;               m = 8 >> spec.w0[k]; }
            float2 u00 = smat[k][0], u01 = smat[k][1];
            float2 u10 = smat[k][2], u11 = smat[k][3];
            float px = __shfl_xor_sync(0xffffffffu, cur.x, m);
            float py = __shfl_xor_sync(0xffffffffu, cur.y, m);
            float2 po = make_float2(px, py);
            bool hi = (state & m) != 0;
            float2 a = hi ? po : cur;
            float2 b = hi ? cur : po;
            float2 nv = hi ? cadd(cmul(u10, a), cmul(u11, b))
                           : cadd(cmul(u00, a), cmul(u01, b));
            bool apply = (mc == 0) | ((state & mc) != 0);
            if (apply) cur = nv;
        }
        sU[state * 17 + col] = cur;
    }
    __syncthreads();

    // ---- phase 2: per-warp image processing (shfl only) ----
    int gw = blockIdx.x * (QBLK / 32) + (tid >> 5);
    int stride = gridDim.x * (QBLK / 32);
    int row = lane & 15;

    for (int img = gw; img < B; img += stride) {
        float v = (lane < 16) ? g_pool[img * 16 + lane] : 0.f;
        // encoder: each lane computes wire (lane&3); ry(a), rz(b), rx(c), ry(d)
        int wsel = lane & 3;
        float aa = __shfl_sync(0xffffffffu, v, wsel);
        float bb = __shfl_sync(0xffffffffu, v, wsel + 4);
        float cc = __shfl_sync(0xffffffffu, v, wsel + 8);
        float dd = __shfl_sync(0xffffffffu, v, wsel + 12);
        float sa, ca, sb, cb, sc, ccs, sd, cd;
        sincosf(0.5f * aa, &sa, &ca);
        sincosf(0.5f * bb, &sb, &cb);
        sincosf(0.5f * cc, &sc, &ccs);
        sincosf(0.5f * dd, &sd, &cd);
        float2 v0 = make_float2(ca * cb, -ca * sb);
        float2 v1 = make_float2(sa * cb, sa * sb);
        float2 t0 = make_float2(ccs * v0.x + sc * v1.y, ccs * v0.y - sc * v1.x);
        float2 t1 = make_float2(sc * v0.y + ccs * v1.x, -sc * v0.x + ccs * v1.y);
        float2 u0 = make_float2(cd * t0.x - sd * t1.x, cd * t0.y - sd * t1.y);
        float2 u1 = make_float2(sd * t0.x + cd * t1.x, sd * t0.y + cd * t1.y);
        // gather per-wire factor for this lane's basis state
        float2 f[4];
#pragma unroll
        for (int w = 0; w < 4; w++) {
            float x0 = __shfl_sync(0xffffffffu, u0.x, w);
            float y0 = __shfl_sync(0xffffffffu, u0.y, w);
            float x1 = __shfl_sync(0xffffffffu, u1.x, w);
            float y1 = __shfl_sync(0xffffffffu, u1.y, w);
            int bit = (lane >> (3 - w)) & 1;
            f[w] = bit ? make_float2(x1, y1) : make_float2(x0, y0);
        }
        float2 phi = cmul(cmul(f[0], f[1]), cmul(f[2], f[3]));
        // psi[row] = sum_j U[row][j] * phi[j]  (phi[j] lives in lane j)
        float2 psi = make_float2(0.f, 0.f);
#pragma unroll
        for (int j = 0; j < 16; j++) {
            float bx = __shfl_sync(0xffffffffu, phi.x, j);
            float by = __shfl_sync(0xffffffffu, phi.y, j);
            psi = cfma_(sU[row * 17 + j], make_float2(bx, by), psi);
        }
        float p = (lane < 16) ? (psi.x * psi.x + psi.y * psi.y) : 0.f;
#pragma unroll
        for (int w = 0; w < 4; w++) {
            float sgn = ((lane >> (3 - w)) & 1) ? -p : p;
#pragma unroll
            for (int off = 16; off > 0; off >>= 1)
                sgn += __shfl_xor_sync(0xffffffffu, sgn, off);
            if (lane == 0) g_z[img * 4 + w] = sgn;
        }
    }
}

// --------------- K2: BN stats + fold + write outputs (merged) --------------
#define RT 512
__global__ void k_reduce(const float* __restrict__ gam, const float* __restrict__ bet,
                         const float* __restrict__ fcw, const float* __restrict__ fcb,
                         float* __restrict__ out, int B) {
    __shared__ double red[RT * 8];
    __shared__ float scoef[5];
    int tid = threadIdx.x;
    double sm[4] = {0, 0, 0, 0}, sq[4] = {0, 0, 0, 0};
    for (int r = tid; r < B; r += RT) {
#pragma unroll
        for (int j = 0; j < 4; j++) {
            double v = (double)g_z[r * 4 + j];
            sm[j] += v;
            sq[j] += v * v;
        }
    }
#pragma unroll
    for (int j = 0; j < 4; j++) { red[tid * 8 + j] = sm[j]; red[tid * 8 + 4 + j] = sq[j]; }
    __syncthreads();
    for (int s = RT / 2; s > 0; s >>= 1) {
        if (tid < s) {
#pragma unroll
            for (int j = 0; j < 8; j++) red[tid * 8 + j] += red[(tid + s) * 8 + j];
        }
        __syncthreads();
    }
    if (tid == 0) {
        double invB = 1.0 / (double)B;
        double csum = (double)fcb[0];
        for (int j = 0; j < 4; j++) {
            double mu = red[j] * invB;
            double var = red[4 + j] * invB - mu * mu;
            double sc = (double)gam[j] / sqrt(var + 1e-5);
            scoef[j] = (float)((double)fcw[j] * sc);
            csum += (double)fcw[j] * ((double)bet[j] - mu * sc);
        }
        scoef[4] = (float)csum;
    }
    __syncthreads();
    float c0 = scoef[0], c1 = scoef[1], c2 = scoef[2], c3 = scoef[3], c4 = scoef[4];
    for (int b = tid; b < B; b += RT) {
        out[b] = c4 + c0 * g_z[b * 4 + 0] + c1 * g_z[b * 4 + 1]
                    + c2 * g_z[b * 4 + 2] + c3 * g_z[b * 4 + 3];
    }
}

// ------------------- host-side MT19937 spec generation ---------------------
static unsigned host_mt_next(unsigned* mt, int* mti) {
    if (*mti >= 624) {
        for (int i = 0; i < 624; i++) {
            unsigned y = (mt[i] & 0x80000000u) | (mt[(i + 1) % 624] & 0x7fffffffu);
            unsigned v = mt[(i + 397) % 624] ^ (y >> 1);
            if (y & 1u) v ^= 0x9908b0dfu;
            mt[i] = v;
        }
        *mti = 0;
    }
    unsigned y = mt[(*mti)++];
    y ^= y >> 11;
    y ^= (y << 7) & 0x9d2c5680u;
    y ^= (y << 15) & 0xefc60000u;
    y ^= y >> 18;
    return y;
}

static void host_build_spec(GateSpec* s) {
    unsigned mt[624];
    mt[0] = 12345u;
    for (int i = 1; i < 624; i++)
        mt[i] = 1812433253u * (mt[i - 1] ^ (mt[i - 1] >> 30)) + (unsigned)i;
    int mti = 624;
    int p = 0;
    for (int k = 0; k < 50; k++) {
        unsigned g;
        do { g = host_mt_next(mt, &mti) & 7u; } while (g > 4u);
        int w0, w1 = -1;
        if (g >= 3u) {
            int arr[4] = {0, 1, 2, 3};
            for (int i = 3; i >= 1; --i) {
                unsigned mask = (unsigned)i;
                mask |= mask >> 1; mask |= mask >> 2; mask |= mask >> 4;
                unsigned j;
                do { j = host_mt_next(mt, &mti) & mask; } while (j > (unsigned)i);
                int t = arr[i]; arr[i] = arr[j]; arr[j] = t;
            }
            w0 = arr[0]; w1 = arr[1];
        } else {
            w0 = (int)(host_mt_next(mt, &mti) & 3u);
        }
        s->g[k] = (int)g; s->w0[k] = w0; s->w1[k] = w1;
        s->pi[k] = (g == 4u) ? -1 : p++;
    }
    // fixed: rx(gp0,w0), ry(gp1,w1), rz(gp2,w3), crx(gp3,0->2), H(3), SX(2), CNOT(3->0)
    int k = 50;
    s->g[k] = 0; s->w0[k] = 0; s->w1[k] = -1; s->pi[k] = -2; k++;
    s->g[k] = 1; s->w0[k] = 1; s->w1[k] = -1; s->pi[k] = -3; k++;
    s->g[k] = 2; s->w0[k] = 3; s->w1[k] = -1; s->pi[k] = -4; k++;
    s->g[k] = 3; s->w0[k] = 0; s->w1[k] = 2;  s->pi[k] = -5; k++;
    s->g[k] = 5; s->w0[k] = 3; s->w1[k] = -1; s->pi[k] = -1; k++;
    s->g[k] = 6; s->w0[k] = 2; s->w1[k] = -1; s->pi[k] = -1; k++;
    s->g[k] = 4; s->w0[k] = 3; s->w1[k] = 0;  s->pi[k] = -1; k++;
}

extern "C" void kernel_launch(void* const* d_in, const int* in_sizes, int n_in,
                              void* d_out, int out_size) {
    const float* x   = (const float*)d_in[0];
    const float* c1w = (const float*)d_in[1];
    const float* c1b = (const float*)d_in[2];
    const float* c2w = (const float*)d_in[3];
    const float* c2b = (const float*)d_in[4];
    const float* gp  = (const float*)d_in[5];
    const float* rp  = (const float*)d_in[6];
    const float* gam = (const float*)d_in[7];
    const float* bet = (const float*)d_in[8];
    const float* fcw = (const float*)d_in[9];
    const float* fcb = (const float*)d_in[10];

    int B = in_sizes[0] / 784;
    if (B > BMAX) B = BMAX;

    GateSpec spec;
    host_build_spec(&spec);

    k_main<<<B, 128>>>(x, c1w, c1b, c2w, c2b);
    int qblocks = (B + 4 * (QBLK / 32) - 1) / (4 * (QBLK / 32));
    if (qblocks < 1) qblocks = 1;
    k_quant<<<qblocks, QBLK>>>(gp, rp, spec, B);
    k_reduce<<<1, RT>>>(gam, bet, fcw, fcb, (float*)d_out, B);
}

// round 17
// speedup vs baseline: 1.5086x; 1.0016x over previous
#include <cuda_runtime.h>
#include <math.h>
#include <string.h>

// ---------------------------------------------------------------------------
// FraudNATHybridModel — R14: R13 with the k_quant mask-precedence bug fixed
// (m = 8 >> w0, not 8 >> (8 >> w0)). k_setup deleted; k_main ends at pooled
// features; k_quant recomputes U per-block (shfl butterflies) and processes
// 4 images per warp; merged reduce+output.
// ---------------------------------------------------------------------------

#define BMAX 8192
#define NGATES 57

struct GateSpec {
    int g[NGATES];    // 0 rx, 1 ry, 2 rz, 3 crx, 4 cnot, 5 H, 6 SX
    int w0[NGATES];
    int w1[NGATES];
    int pi[NGATES];   // >=0: rand_params[pi]; -2-j: gate_params[j]; -1: none
};

__device__ float  g_pool[BMAX * 16];
__device__ float  g_z[BMAX * 4];

#define PACK2(out, lo, hi) \
    asm("mov.b64 %0, {%1, %2};" : "=l"(out) : "r"(__float_as_uint(lo)), "r"(__float_as_uint(hi)))
#define UNPACK2(lo, hi, in) \
    do { unsigned _ulo, _uhi; \
         asm("mov.b64 {%0, %1}, %2;" : "=r"(_ulo), "=r"(_uhi) : "l"(in)); \
         lo = __uint_as_float(_ulo); hi = __uint_as_float(_uhi); } while (0)
#define FMA2(acc, a, b) \
    asm("fma.rn.f32x2 %0, %1, %2, %0;" : "+l"(acc) : "l"(a), "l"(b))

__device__ __forceinline__ unsigned long long lds64(const void* p) {
    unsigned long long v;
    unsigned a = (unsigned)__cvta_generic_to_shared(p);
    asm("ld.shared.b64 %0, [%1];" : "=l"(v) : "r"(a));
    return v;
}

__device__ __forceinline__ float2 cmul(float2 a, float2 b) {
    return make_float2(a.x * b.x - a.y * b.y, a.x * b.y + a.y * b.x);
}
__device__ __forceinline__ float2 cadd(float2 a, float2 b) {
    return make_float2(a.x + b.x, a.y + b.y);
}
__device__ __forceinline__ float2 cfma_(float2 a, float2 b, float2 c) {
    c.x += a.x * b.x - a.y * b.y;
    c.y += a.x * b.y + a.y * b.x;
    return c;
}

// ------------------------- K1: fused conv pipeline -------------------------
__global__ __launch_bounds__(128) void k_main(const float* __restrict__ x,
                                              const float* __restrict__ w1,
                                              const float* __restrict__ b1,
                                              const float* __restrict__ w2,
                                              const float* __restrict__ b2) {
    __shared__ __align__(16) float2 sxp[29][31];  // (x[j-1][c-1], x[j][c-1]), zero-padded
    __shared__ float2 sw1p[72];          // (w,w)
    __shared__ float2 sb1p[8];           // (b,b)
    __shared__ float sh1[8 * 196];       // conv1 pooled output [8][14][14]
    __shared__ __align__(16) float sw2c2[1152];  // conv2 weights [k][oc]
    __shared__ float sb2[16];
    __shared__ float shm[16 * 14 * 7];   // conv2 horizontally-pooled rows
    __shared__ float spart[112];

    int tid = threadIdx.x;
    int b = blockIdx.x;
    const float* xb = x + (size_t)b * 784;

    // zero sxp
    {
        float2 z2 = make_float2(0.f, 0.f);
        float2* p1 = &sxp[0][0];
        for (int i = tid; i < 29 * 31; i += 128) p1[i] = z2;
    }
    for (int i = tid; i < 72; i += 128) { float w = w1[i]; sw1p[i] = make_float2(w, w); }
    if (tid < 8)  { float v = b1[tid]; sb1p[tid] = make_float2(v, v); }
    for (int i = tid; i < 1152; i += 128) {
        int k = i >> 4, oc = i & 15;
        sw2c2[i] = w2[oc * 72 + k];      // transpose to [k][oc]
    }
    if (tid < 16) sb2[tid] = b2[tid];
    __syncthreads();

    // scatter input into vertical pairs
    for (int i = tid; i < 784; i += 128) {
        int r = i / 28, c = i % 28;
        float v = xb[i];
        sxp[r + 1][c + 1].x = v;
        sxp[r][c + 1].y = v;
    }
    __syncthreads();

    // ---- conv1 (packed vertical row pairs) + relu + maxpool -> sh1 ----
    if (tid < 112) {
        int c = tid / 14, y = tid % 14;
        unsigned long long wp[9];
#pragma unroll
        for (int k = 0; k < 9; k++) wp[k] = lds64(&sw1p[c * 9 + k]);
        unsigned long long bias2 = lds64(&sb1p[c]);
        float pooled[14];
#pragma unroll
        for (int h = 0; h < 2; h++) {
            unsigned long long cr[14];
#pragma unroll
            for (int i = 0; i < 14; i++) cr[i] = bias2;
#pragma unroll
            for (int ky = 0; ky < 3; ky++) {
                int j = 2 * y + ky;
                unsigned long long rp[16];
#pragma unroll
                for (int i = 0; i < 16; i++) rp[i] = lds64(&sxp[j][14 * h + i]);
#pragma unroll
                for (int kx = 0; kx < 3; kx++) {
                    unsigned long long w = wp[ky * 3 + kx];
#pragma unroll
                    for (int i = 0; i < 14; i++) FMA2(cr[i], w, rp[i + kx]);
                }
            }
#pragma unroll
            for (int o = 0; o < 7; o++) {
                float l0, h0, l1, h1;
                UNPACK2(l0, h0, cr[2 * o]);
                UNPACK2(l1, h1, cr[2 * o + 1]);
                pooled[h * 7 + o] = fmaxf(fmaxf(fmaxf(l0, h0), fmaxf(l1, h1)), 0.f);
            }
        }
        float* row = &sh1[(c * 14 + y) * 14];
#pragma unroll
        for (int i = 0; i < 14; i++) row[i] = pooled[i];
    }
    __syncthreads();

    // ---- conv2 (8->16) packed f32x2 over channel pairs ----
    if (tid < 112) {
        int cp = tid / 14, y = tid % 14;
        unsigned long long acc[14];
        {
            unsigned long long bias2;
            PACK2(bias2, sb2[2 * cp], sb2[2 * cp + 1]);
#pragma unroll
            for (int i = 0; i < 14; i++) acc[i] = bias2;
        }
#pragma unroll
        for (int ic = 0; ic < 8; ic++) {
#pragma unroll
            for (int ky = 0; ky < 3; ky++) {
                int iy = y + ky - 1;
                if (iy >= 0 && iy < 14) {
                    unsigned long long rp[16];
                    rp[0] = 0ull; rp[15] = 0ull;
#pragma unroll
                    for (int i = 0; i < 14; i++) {
                        float v = sh1[(ic * 14 + iy) * 14 + i];
                        PACK2(rp[i + 1], v, v);
                    }
#pragma unroll
                    for (int kx = 0; kx < 3; kx++) {
                        float2 wf = *(const float2*)&sw2c2[((ic * 3 + ky) * 3 + kx) * 16 + 2 * cp];
                        unsigned long long w2p;
                        PACK2(w2p, wf.x, wf.y);
#pragma unroll
                        for (int i = 0; i < 14; i++)
                            FMA2(acc[i], w2p, rp[i + kx]);
                    }
                }
            }
        }
#pragma unroll
        for (int i = 0; i < 7; i++) {
            float a0l, a1l, a0h, a1h;
            UNPACK2(a0l, a1l, acc[2 * i]);
            UNPACK2(a0h, a1h, acc[2 * i + 1]);
            shm[((2 * cp) * 14 + y) * 7 + i]     = fmaxf(a0l, a0h);
            shm[((2 * cp + 1) * 14 + y) * 7 + i] = fmaxf(a1l, a1h);
        }
    }
    __syncthreads();

    // ---- vertical max of row pairs + relu + row sum -> spart ----
    if (tid < 112) {
        int c = tid / 7, y2 = tid % 7;
        const float* r0 = &shm[(c * 14 + 2 * y2) * 7];
        const float* r1 = r0 + 7;
        float psum = 0.f;
#pragma unroll
        for (int i = 0; i < 7; i++)
            psum += fmaxf(fmaxf(r0[i], r1[i]), 0.f);
        spart[c * 7 + y2] = psum;
    }
    __syncthreads();

    if (tid < 16) {
        float s = 0.f;
#pragma unroll
        for (int j = 0; j < 7; j++) s += spart[tid * 7 + j];
        g_pool[b * 16 + tid] = s * (1.f / 49.f);
    }
}

// ---------------- K_quant: per-block U (shfl) + per-warp images ------------
#define QBLK 256
__global__ __launch_bounds__(QBLK) void k_quant(const float* __restrict__ gate_params,
                                                const float* __restrict__ rand_params,
                                                GateSpec spec, int B) {
    __shared__ float2 smat[NGATES][4];
    __shared__ float2 sU[16 * 17];       // U[row][col] at row*17+col (conflict-free)
    int tid = threadIdx.x;
    int lane = tid & 31;

    // ---- phase 1a: gate matrices ----
    if (tid < NGATES) {
        int g = spec.g[tid];
        int pi = spec.pi[tid];
        float t = 0.f;
        if (pi >= 0) t = rand_params[pi];
        else if (pi <= -2) t = gate_params[-2 - pi];
        float sn, cs;
        sincosf(0.5f * t, &sn, &cs);
        float2 u00, u01, u10, u11;
        if (g == 0 || g == 3) {
            u00 = make_float2(cs, 0.f);  u01 = make_float2(0.f, -sn);
            u10 = make_float2(0.f, -sn); u11 = make_float2(cs, 0.f);
        } else if (g == 1) {
            u00 = make_float2(cs, 0.f);  u01 = make_float2(-sn, 0.f);
            u10 = make_float2(sn, 0.f);  u11 = make_float2(cs, 0.f);
        } else if (g == 2) {
            u00 = make_float2(cs, -sn);  u01 = make_float2(0.f, 0.f);
            u10 = make_float2(0.f, 0.f); u11 = make_float2(cs, sn);
        } else if (g == 4) {
            u00 = make_float2(0.f, 0.f); u01 = make_float2(1.f, 0.f);
            u10 = make_float2(1.f, 0.f); u11 = make_float2(0.f, 0.f);
        } else if (g == 5) {
            const float r = 0.70710678118654752f;
            u00 = make_float2(r, 0.f);   u01 = make_float2(r, 0.f);
            u10 = make_float2(r, 0.f);   u11 = make_float2(-r, 0.f);
        } else {
            u00 = make_float2(0.5f, 0.5f);  u01 = make_float2(0.5f, -0.5f);
            u10 = make_float2(0.5f, -0.5f); u11 = make_float2(0.5f, 0.5f);
        }
        smat[tid][0] = u00; smat[tid][1] = u01;
        smat[tid][2] = u10; smat[tid][3] = u11;
    }
    __syncthreads();

    // ---- phase 1b: shfl-butterfly gate chain; 256 threads = 16x16 entries --
    {
        int col = (tid >> 5) * 2 + (lane >> 4);
        int state = lane & 15;
        float2 cur = make_float2(state == col ? 1.f : 0.f, 0.f);
        for (int k = 0; k < NGATES; k++) {
            int g = spec.g[k];
            int m, mc;
            if (g == 3 || g == 4) { mc = 8 >> spec.w0[k]; m = 8 >> spec.w1[k]; }
            else                  { mc = 0;               m = 8 >> spec.w0[k]; }
            float2 u00 = smat[k][0], u01 = smat[k][1];
            float2 u10 = smat[k][2], u11 = smat[k][3];
            float px = __shfl_xor_sync(0xffffffffu, cur.x, m);
            float py = __shfl_xor_sync(0xffffffffu, cur.y, m);
            float2 po = make_float2(px, py);
            bool hi = (state & m) != 0;
            float2 a = hi ? po : cur;
            float2 b = hi ? cur : po;
            float2 nv = hi ? cadd(cmul(u10, a), cmul(u11, b))
                           : cadd(cmul(u00, a), cmul(u01, b));
            bool apply = (mc == 0) | ((state & mc) != 0);
            if (apply) cur = nv;
        }
        sU[state * 17 + col] = cur;
    }
    __syncthreads();

    // ---- phase 2: per-warp image processing (shfl only) ----
    int gw = blockIdx.x * (QBLK / 32) + (tid >> 5);
    int stride = gridDim.x * (QBLK / 32);
    int row = lane & 15;

    for (int img = gw; img < B; img += stride) {
        float v = (lane < 16) ? g_pool[img * 16 + lane] : 0.f;
        // encoder: each lane computes wire (lane&3); ry(a), rz(b), rx(c), ry(d)
        int wsel = lane & 3;
        float aa = __shfl_sync(0xffffffffu, v, wsel);
        float bb = __shfl_sync(0xffffffffu, v, wsel + 4);
        float cc = __shfl_sync(0xffffffffu, v, wsel + 8);
        float dd = __shfl_sync(0xffffffffu, v, wsel + 12);
        float sa, ca, sb, cb, sc, ccs, sd, cd;
        sincosf(0.5f * aa, &sa, &ca);
        sincosf(0.5f * bb, &sb, &cb);
        sincosf(0.5f * cc, &sc, &ccs);
        sincosf(0.5f * dd, &sd, &cd);
        float2 v0 = make_float2(ca * cb, -ca * sb);
        float2 v1 = make_float2(sa * cb, sa * sb);
        float2 t0 = make_float2(ccs * v0.x + sc * v1.y, ccs * v0.y - sc * v1.x);
        float2 t1 = make_float2(sc * v0.y + ccs * v1.x, -sc * v0.x + ccs * v1.y);
        float2 u0 = make_float2(cd * t0.x - sd * t1.x, cd * t0.y - sd * t1.y);
        float2 u1 = make_float2(sd * t0.x + cd * t1.x, sd * t0.y + cd * t1.y);
        // gather per-wire factor for this lane's basis state
        float2 f[4];
#pragma unroll
        for (int w = 0; w < 4; w++) {
            float x0 = __shfl_sync(0xffffffffu, u0.x, w);
            float y0 = __shfl_sync(0xffffffffu, u0.y, w);
            float x1 = __shfl_sync(0xffffffffu, u1.x, w);
            float y1 = __shfl_sync(0xffffffffu, u1.y, w);
            int bit = (lane >> (3 - w)) & 1;
            f[w] = bit ? make_float2(x1, y1) : make_float2(x0, y0);
        }
        float2 phi = cmul(cmul(f[0], f[1]), cmul(f[2], f[3]));
        // psi[row] = sum_j U[row][j] * phi[j]  (phi[j] lives in lane j)
        float2 psi = make_float2(0.f, 0.f);
#pragma unroll
        for (int j = 0; j < 16; j++) {
            float bx = __shfl_sync(0xffffffffu, phi.x, j);
            float by = __shfl_sync(0xffffffffu, phi.y, j);
            psi = cfma_(sU[row * 17 + j], make_float2(bx, by), psi);
        }
        float p = (lane < 16) ? (psi.x * psi.x + psi.y * psi.y) : 0.f;
#pragma unroll
        for (int w = 0; w < 4; w++) {
            float sgn = ((lane >> (3 - w)) & 1) ? -p : p;
#pragma unroll
            for (int off = 16; off > 0; off >>= 1)
                sgn += __shfl_xor_sync(0xffffffffu, sgn, off);
            if (lane == 0) g_z[img * 4 + w] = sgn;
        }
    }
}

// --------------- K2: BN stats + fold + write outputs (merged) --------------
#define RT 512
__global__ void k_reduce(const float* __restrict__ gam, const float* __restrict__ bet,
                         const float* __restrict__ fcw, const float* __restrict__ fcb,
                         float* __restrict__ out, int B) {
    __shared__ double red[RT * 8];
    __shared__ float scoef[5];
    int tid = threadIdx.x;
    double sm[4] = {0, 0, 0, 0}, sq[4] = {0, 0, 0, 0};
    for (int r = tid; r < B; r += RT) {
#pragma unroll
        for (int j = 0; j < 4; j++) {
            double v = (double)g_z[r * 4 + j];
            sm[j] += v;
            sq[j] += v * v;
        }
    }
#pragma unroll
    for (int j = 0; j < 4; j++) { red[tid * 8 + j] = sm[j]; red[tid * 8 + 4 + j] = sq[j]; }
    __syncthreads();
    for (int s = RT / 2; s > 0; s >>= 1) {
        if (tid < s) {
#pragma unroll
            for (int j = 0; j < 8; j++) red[tid * 8 + j] += red[(tid + s) * 8 + j];
        }
        __syncthreads();
    }
    if (tid == 0) {
        double invB = 1.0 / (double)B;
        double csum = (double)fcb[0];
        for (int j = 0; j < 4; j++) {
            double mu = red[j] * invB;
            double var = red[4 + j] * invB - mu * mu;
            double sc = (double)gam[j] / sqrt(var + 1e-5);
            scoef[j] = (float)((double)fcw[j] * sc);
            csum += (double)fcw[j] * ((double)bet[j] - mu * sc);
        }
        scoef[4] = (float)csum;
    }
    __syncthreads();
    float c0 = scoef[0], c1 = scoef[1], c2 = scoef[2], c3 = scoef[3], c4 = scoef[4];
    for (int b = tid; b < B; b += RT) {
        out[b] = c4 + c0 * g_z[b * 4 + 0] + c1 * g_z[b * 4 + 1]
                    + c2 * g_z[b * 4 + 2] + c3 * g_z[b * 4 + 3];
    }
}

// ------------------- host-side MT19937 spec generation ---------------------
static unsigned host_mt_next(unsigned* mt, int* mti) {
    if (*mti >= 624) {
        for (int i = 0; i < 624; i++) {
            unsigned y = (mt[i] & 0x80000000u) | (mt[(i + 1) % 624] & 0x7fffffffu);
            unsigned v = mt[(i + 397) % 624] ^ (y >> 1);
            if (y & 1u) v ^= 0x9908b0dfu;
            mt[i] = v;
        }
        *mti = 0;
    }
    unsigned y = mt[(*mti)++];
    y ^= y >> 11;
    y ^= (y << 7) & 0x9d2c5680u;
    y ^= (y << 15) & 0xefc60000u;
    y ^= y >> 18;
    return y;
}

static void host_build_spec(GateSpec* s) {
    unsigned mt[624];
    mt[0] = 12345u;
    for (int i = 1; i < 624; i++)
        mt[i] = 1812433253u * (mt[i - 1] ^ (mt[i - 1] >> 30)) + (unsigned)i;
    int mti = 624;
    int p = 0;
    for (int k = 0; k < 50; k++) {
        unsigned g;
        do { g = host_mt_next(mt, &mti) & 7u; } while (g > 4u);
        int w0, w1 = -1;
        if (g >= 3u) {
            int arr[4] = {0, 1, 2, 3};
            for (int i = 3; i >= 1; --i) {
                unsigned mask = (unsigned)i;
                mask |= mask >> 1; mask |= mask >> 2; mask |= mask >> 4;
                unsigned j;
                do { j = host_mt_next(mt, &mti) & mask; } while (j > (unsigned)i);
                int t = arr[i]; arr[i] = arr[j]; arr[j] = t;
            }
            w0 = arr[0]; w1 = arr[1];
        } else {
            w0 = (int)(host_mt_next(mt, &mti) & 3u);
        }
        s->g[k] = (int)g; s->w0[k] = w0; s->w1[k] = w1;
        s->pi[k] = (g == 4u) ? -1 : p++;
    }
    // fixed: rx(gp0,w0), ry(gp1,w1), rz(gp2,w3), crx(gp3,0->2), H(3), SX(2), CNOT(3->0)
    int k = 50;
    s->g[k] = 0; s->w0[k] = 0; s->w1[k] = -1; s->pi[k] = -2; k++;
    s->g[k] = 1; s->w0[k] = 1; s->w1[k] = -1; s->pi[k] = -3; k++;
    s->g[k] = 2; s->w0[k] = 3; s->w1[k] = -1; s->pi[k] = -4; k++;
    s->g[k] = 3; s->w0[k] = 0; s->w1[k] = 2;  s->pi[k] = -5; k++;
    s->g[k] = 5; s->w0[k] = 3; s->w1[k] = -1; s->pi[k] = -1; k++;
    s->g[k] = 6; s->w0[k] = 2; s->w1[k] = -1; s->pi[k] = -1; k++;
    s->g[k] = 4; s->w0[k] = 3; s->w1[k] = 0;  s->pi[k] = -1; k++;
}

extern "C" void kernel_launch(void* const* d_in, const int* in_sizes, int n_in,
                              void* d_out, int out_size) {
    const float* x   = (const float*)d_in[0];
    const float* c1w = (const float*)d_in[1];
    const float* c1b = (const float*)d_in[2];
    const float* c2w = (const float*)d_in[3];
    const float* c2b = (const float*)d_in[4];
    const float* gp  = (const float*)d_in[5];
    const float* rp  = (const float*)d_in[6];
    const float* gam = (const float*)d_in[7];
    const float* bet = (const float*)d_in[8];
    const float* fcw = (const float*)d_in[9];
    const float* fcb = (const float*)d_in[10];

    int B = in_sizes[0] / 784;
    if (B > BMAX) B = BMAX;

    GateSpec spec;
    host_build_spec(&spec);

    k_main<<<B, 128>>>(x, c1w, c1b, c2w, c2b);
    int qblocks = (B + 4 * (QBLK / 32) - 1) / (4 * (QBLK / 32));
    if (qblocks < 1) qblocks = 1;
    k_quant<<<qblocks, QBLK>>>(gp, rp, spec, B);
    k_reduce<<<1, RT>>>(gam, bet, fcw, fcb, (float*)d_out, B);
}